// round 4
// baseline (speedup 1.0000x reference)
#include <cuda_runtime.h>
#include <math.h>

#define BS 32
#define NN 256
#define EE 64
#define CC 512
#define HH 4
#define LL 2
#define MM 65

// ---------------- scratch (static device globals; no allocation) ----------------
__device__ float g_eattr[(size_t)BS*MM*CC];              // [b,m,c]
__device__ float g_xl[(size_t)BS*NN*HH*CC];              // [b,n,h,c]
__device__ float g_el[(size_t)BS*MM*HH*CC];              // [b,m,h,c]
__device__ float g_an[BS*NN*HH];                         // [b,n,h]
__device__ float g_ae[BS*MM*HH];                         // [b,m,h]
__device__ float g_alpha_nm[(size_t)BS*HH*NN*MM];        // [b,h,n,m]
__device__ float g_alpha_mn[(size_t)BS*HH*MM*NN];        // [b,h,m,n]
__device__ float g_msge[(size_t)BS*HH*MM*CC];            // [b,h,m,c]
__device__ float g_ohp[(size_t)BS*HH*NN*CC];             // [b,h,n,c]
__device__ float g_xw[(size_t)2*BS*NN*CC];               // [r,b,n,c]
__device__ float g_xroot[(size_t)BS*NN*CC];              // [b,n,c]
__device__ float g_xr[(size_t)BS*NN*CC];
__device__ float g_xh[(size_t)BS*NN*CC];
__device__ unsigned char g_adj_idx[(size_t)BS*2*NN*NN];  // per (b,r,j): source list
__device__ int   g_adj_cnt[BS*2*NN];
__device__ float g_invdeg[BS*2*NN];
__device__ float g_invD[BS*NN];
__device__ float g_invB[BS*MM];
__device__ float g_ctx[BS*2*CC];
__device__ float g_h1[BS*2*CC];
__device__ float g_ctx2[BS*2*CC];

// ---------------- generic batched SGEMM: C = A @ B (row-major) ----------------
// 128x128 tile, BK=8, 8x8 per thread, 256 threads. Guarded loads/stores for
// arbitrary M/N/K. Batch z decomposed as z1 = z/zdiv, z2 = z%zdiv with separate
// strides (handles the [b,h] slicing of xl without a transpose).
__global__ void sgemm_kernel(const float* __restrict__ A, const float* __restrict__ B,
                             float* __restrict__ C,
                             int Mr, int Nc, int K, int lda, int ldb, int ldc,
                             int zdiv,
                             long long sA1, long long sA2,
                             long long sB1, long long sB2,
                             long long sC1, long long sC2)
{
    int z = blockIdx.z;
    int z1 = z / zdiv, z2 = z % zdiv;
    A += z1 * sA1 + z2 * sA2;
    B += z1 * sB1 + z2 * sB2;
    C += z1 * sC1 + z2 * sC2;

    __shared__ float As[8][128];
    __shared__ float Bs[8][128];

    const int tid = threadIdx.x;          // 256
    const int tx = tid & 15;              // 0..15 (cols)
    const int ty = tid >> 4;              // 0..15 (rows)
    const int rowBase = blockIdx.y * 128;
    const int colBase = blockIdx.x * 128;

    // A tile loads: 128x8, 4 per thread
    const int aRow = tid >> 1;            // 0..127
    const int aCol = (tid & 1) * 4;       // 0 or 4
    // B tile loads: 8x128, 4 per thread
    const int bRow = tid >> 5;            // 0..7
    const int bCol = (tid & 31) * 4;      // 0..124

    float acc[8][8];
    #pragma unroll
    for (int i = 0; i < 8; i++)
        #pragma unroll
        for (int j = 0; j < 8; j++) acc[i][j] = 0.f;

    for (int k0 = 0; k0 < K; k0 += 8) {
        #pragma unroll
        for (int j = 0; j < 4; j++) {
            int gr = rowBase + aRow;
            int gc = k0 + aCol + j;
            float v = 0.f;
            if (gr < Mr && gc < K) v = A[(size_t)gr * lda + gc];
            As[aCol + j][aRow] = v;
        }
        #pragma unroll
        for (int j = 0; j < 4; j++) {
            int gr = k0 + bRow;
            int gc = colBase + bCol + j;
            float v = 0.f;
            if (gr < K && gc < Nc) v = B[(size_t)gr * ldb + gc];
            Bs[bRow][bCol + j] = v;
        }
        __syncthreads();
        #pragma unroll
        for (int kk = 0; kk < 8; kk++) {
            float ra[8], rb[8];
            #pragma unroll
            for (int i = 0; i < 8; i++) ra[i] = As[kk][ty * 8 + i];
            #pragma unroll
            for (int j = 0; j < 8; j++) rb[j] = Bs[kk][tx * 8 + j];
            #pragma unroll
            for (int i = 0; i < 8; i++)
                #pragma unroll
                for (int j = 0; j < 8; j++)
                    acc[i][j] += ra[i] * rb[j];
        }
        __syncthreads();
    }

    #pragma unroll
    for (int i = 0; i < 8; i++) {
        int gr = rowBase + ty * 8 + i;
        if (gr >= Mr) continue;
        #pragma unroll
        for (int j = 0; j < 8; j++) {
            int gc = colBase + tx * 8 + j;
            if (gc < Nc) C[(size_t)gr * ldc + gc] = acc[i][j];
        }
    }
}

static void sgemm(const float* A, const float* B, float* C,
                  int Mr, int Nc, int K, int lda, int ldb, int ldc,
                  int batch, int zdiv,
                  long long sA1, long long sA2, long long sB1, long long sB2,
                  long long sC1, long long sC2)
{
    dim3 grid((Nc + 127) / 128, (Mr + 127) / 128, batch);
    sgemm_kernel<<<grid, 256>>>(A, B, C, Mr, Nc, K, lda, ldb, ldc,
                                zdiv, sA1, sA2, sB1, sB2, sC1, sC2);
}

// ---------------- prep kernels (layer-invariant) ----------------
__global__ void prep_eattr_kernel(const float* __restrict__ pooled,
                                  const float* __restrict__ svo) {
    int idx = blockIdx.x * blockDim.x + threadIdx.x;
    if (idx >= BS * MM * CC) return;
    int c = idx % CC;
    int bm = idx / CC;
    int m = bm % MM, b = bm / MM;
    g_eattr[idx] = (m == 0) ? pooled[b * CC + c]
                            : svo[((size_t)(b * EE + (m - 1))) * CC + c];
}

__global__ void prep_adj_kernel(const int* __restrict__ aug,
                                const int* __restrict__ punct) {
    int idx = blockIdx.x * blockDim.x + threadIdx.x;   // (b*2+r)*NN + j
    if (idx >= BS * 2 * NN) return;
    int j = idx % NN;
    int br = idx / NN;
    int r = br & 1, b = br >> 1;
    unsigned char* lst = g_adj_idx + (size_t)idx * NN;
    int cnt = 0;
    for (int i = 0; i < NN; i++) {
        int a = aug[((size_t)(b * NN + i)) * NN + j];
        int v = (r == 1) ? a : (punct[((size_t)(b * NN + i)) * NN + j] * (1 - a));
        if (v) lst[cnt++] = (unsigned char)i;
    }
    g_adj_cnt[idx] = cnt;
    g_invdeg[idx] = (cnt > 0) ? 1.f / (float)cnt : 0.f;
}

__global__ void prep_deg_kernel(const int* __restrict__ s2w) {
    int idx = blockIdx.x * blockDim.x + threadIdx.x;
    if (idx < BS * NN) {
        const int* row = s2w + (size_t)idx * EE;
        int s = 1;                               // global hyperedge
        for (int e = 0; e < EE; e++) s += row[e];
        g_invD[idx] = 1.f / (float)s;            // s >= 1 always
    } else if (idx < BS * NN + BS * MM) {
        int t = idx - BS * NN;
        int m = t % MM, b = t / MM;
        if (m == 0) {
            g_invB[t] = 1.f / (float)NN;
        } else {
            int s = 0;
            for (int n = 0; n < NN; n++) s += s2w[((size_t)(b * NN + n)) * EE + (m - 1)];
            g_invB[t] = (s > 0) ? 1.f / (float)s : 0.f;
        }
    }
}

// ---------------- attention path ----------------
// out[row,h] = dot(X[row,h,:], att[h,:]); one warp per (row,h)
__global__ void attdot_kernel(const float* __restrict__ X,
                              const float* __restrict__ att,
                              float* __restrict__ out) {
    int row = blockIdx.x;
    int h = threadIdx.x >> 5, lane = threadIdx.x & 31;
    const float* x = X + ((size_t)row * HH + h) * CC;
    const float* a = att + h * CC;
    float acc = 0.f;
    for (int c = lane; c < CC; c += 32) acc += x[c] * a[c];
    #pragma unroll
    for (int o = 16; o; o >>= 1) acc += __shfl_xor_sync(0xffffffffu, acc, o);
    if (lane == 0) out[row * HH + h] = acc;
}

// masked softmax over M per (b,n,h); writes both alpha layouts
__global__ void alpha_kernel(const int* __restrict__ s2w) {
    int bn = blockIdx.x;
    int b = bn >> 8, n = bn & 255;
    int h = threadIdx.x >> 5, lane = threadIdx.x & 31;
    float anv = g_an[bn * HH + h];
    float v[3]; int ok[3];
    #pragma unroll
    for (int s = 0; s < 3; s++) {
        int m = lane + s * 32;
        float vv = -1e30f; int o = 0;
        if (m < MM) {
            o = (m == 0) || (s2w[(size_t)bn * EE + (m - 1)] != 0);
            if (o) {
                float x = anv + g_ae[(b * MM + m) * HH + h];
                vv = (x > 0.f) ? x : 0.2f * x;   // leaky_relu 0.2
            }
        }
        v[s] = vv; ok[s] = o;
    }
    float mx = fmaxf(v[0], fmaxf(v[1], v[2]));
    #pragma unroll
    for (int o = 16; o; o >>= 1) mx = fmaxf(mx, __shfl_xor_sync(0xffffffffu, mx, o));
    float e[3]; float sum = 0.f;
    #pragma unroll
    for (int s = 0; s < 3; s++) { e[s] = ok[s] ? expf(v[s] - mx) : 0.f; sum += e[s]; }
    #pragma unroll
    for (int o = 16; o; o >>= 1) sum += __shfl_xor_sync(0xffffffffu, sum, o);
    float inv = 1.f / sum;
    size_t z = (size_t)(b * HH + h);
    #pragma unroll
    for (int s = 0; s < 3; s++) {
        int m = lane + s * 32;
        if (m < MM) {
            float a = e[s] * inv;
            g_alpha_nm[(z * NN + n) * MM + m] = a;
            g_alpha_mn[(z * MM + m) * NN + n] = a;
        }
    }
}

__global__ void scale_msge_kernel() {
    size_t idx = (size_t)blockIdx.x * blockDim.x + threadIdx.x;
    if (idx >= (size_t)BS * HH * MM * CC) return;
    int m = (int)((idx / CC) % MM);
    int b = (int)(idx / ((size_t)HH * MM * CC));
    g_msge[idx] *= g_invB[b * MM + m];
}

// head mean + invD + bias + relu -> xh_out
__global__ void finalize_h_kernel(float* __restrict__ out, const float* __restrict__ bias) {
    int bn = blockIdx.x; int c = threadIdx.x;
    int b = bn >> 8, n = bn & 255;
    float s = 0.f;
    #pragma unroll
    for (int h = 0; h < HH; h++)
        s += g_ohp[(((size_t)(b * HH + h)) * NN + n) * CC + c];
    float v = s * 0.25f * g_invD[bn] + bias[c];
    out[(size_t)bn * CC + c] = (v > 0.f) ? v : 0.f;
}

// ---------------- RGCN combine: sparse gather + root + bias + relu ----------------
__global__ void rgcn_kernel(float* __restrict__ out, const float* __restrict__ bias) {
    int bj = blockIdx.x; int c = threadIdx.x;
    int b = bj >> 8, j = bj & 255;
    float acc = g_xroot[(size_t)bj * CC + c];
    #pragma unroll
    for (int r = 0; r < 2; r++) {
        int e = (b * 2 + r) * NN + j;
        int cnt = g_adj_cnt[e];
        const unsigned char* lst = g_adj_idx + (size_t)e * NN;
        float p = 0.f;
        for (int t = 0; t < cnt; t++) {
            int i = lst[t];
            p += g_xw[(size_t)r * BS * NN * CC + ((size_t)(b * NN + i)) * CC + c];
        }
        acc += p * g_invdeg[e];
    }
    acc += bias[c];
    out[(size_t)bj * CC + c] = (acc > 0.f) ? acc : 0.f;
}

// ---------------- info exchange ----------------
__global__ void build_ctx_kernel(const float* __restrict__ xr, const float* __restrict__ xh) {
    int idx = blockIdx.x * blockDim.x + threadIdx.x;
    if (idx >= BS * 2 * CC) return;
    int c = idx % (2 * CC); int b = idx / (2 * CC);
    g_ctx[idx] = (c < CC) ? xr[(size_t)b * NN * CC + c]
                          : xh[(size_t)b * NN * CC + (c - CC)];
}

// out[b,j] = act(sum_k in[b,k] * W[k,j] + bias[j]); grid (8, BS), 128 threads
__global__ void ie_gemm_kernel(const float* __restrict__ in, const float* __restrict__ W,
                               const float* __restrict__ bias, float* __restrict__ out,
                               int relu) {
    __shared__ float s_in[2 * CC];
    int b = blockIdx.y;
    int j = blockIdx.x * 128 + threadIdx.x;
    for (int t = threadIdx.x; t < 2 * CC; t += 128) s_in[t] = in[b * 2 * CC + t];
    __syncthreads();
    float a0 = 0.f, a1 = 0.f, a2 = 0.f, a3 = 0.f;
    for (int k = 0; k < 2 * CC; k += 4) {
        a0 += s_in[k + 0] * W[(size_t)(k + 0) * (2 * CC) + j];
        a1 += s_in[k + 1] * W[(size_t)(k + 1) * (2 * CC) + j];
        a2 += s_in[k + 2] * W[(size_t)(k + 2) * (2 * CC) + j];
        a3 += s_in[k + 3] * W[(size_t)(k + 3) * (2 * CC) + j];
    }
    float acc = (a0 + a1) + (a2 + a3) + bias[j];
    if (relu) acc = (acc > 0.f) ? acc : 0.f;
    out[b * 2 * CC + j] = acc;
}

__global__ void writeback_kernel(float* __restrict__ xr, float* __restrict__ xh) {
    int idx = blockIdx.x * blockDim.x + threadIdx.x;
    if (idx >= BS * 2 * CC) return;
    int c = idx % (2 * CC); int b = idx / (2 * CC);
    float v = g_ctx2[idx];
    if (c < CC) xr[(size_t)b * NN * CC + c] = v;
    else        xh[(size_t)b * NN * CC + (c - CC)] = v;
}

// ---------------- launch ----------------
extern "C" void kernel_launch(void* const* d_in, const int* in_sizes, int n_in,
                              void* d_out, int out_size) {
    const float* spans  = (const float*)d_in[0];
    const float* svo    = (const float*)d_in[1];
    const float* pooled = (const float*)d_in[2];
    const int*   s2w    = (const int*)d_in[3];
    const int*   aug    = (const int*)d_in[4];
    const int*   punct  = (const int*)d_in[5];
    const float* w_rel  = (const float*)d_in[6];
    const float* w_root = (const float*)d_in[7];
    const float* b_rgcn = (const float*)d_in[8];
    const float* w_lin  = (const float*)d_in[9];
    const float* att_x  = (const float*)d_in[10];
    const float* att_e  = (const float*)d_in[11];
    const float* b_hgcn = (const float*)d_in[12];
    const float* ie_w1  = (const float*)d_in[13];
    const float* ie_b1  = (const float*)d_in[14];
    const float* ie_w2  = (const float*)d_in[15];
    const float* ie_b2  = (const float*)d_in[16];
    float* out = (float*)d_out;

    float *p_eattr, *p_xl, *p_el, *p_an, *p_ae, *p_anm, *p_amn, *p_msge, *p_ohp;
    float *p_xw, *p_xroot, *p_xr, *p_xh, *p_ctx, *p_h1, *p_ctx2;
    cudaGetSymbolAddress((void**)&p_eattr, g_eattr);
    cudaGetSymbolAddress((void**)&p_xl, g_xl);
    cudaGetSymbolAddress((void**)&p_el, g_el);
    cudaGetSymbolAddress((void**)&p_an, g_an);
    cudaGetSymbolAddress((void**)&p_ae, g_ae);
    cudaGetSymbolAddress((void**)&p_anm, g_alpha_nm);
    cudaGetSymbolAddress((void**)&p_amn, g_alpha_mn);
    cudaGetSymbolAddress((void**)&p_msge, g_msge);
    cudaGetSymbolAddress((void**)&p_ohp, g_ohp);
    cudaGetSymbolAddress((void**)&p_xw, g_xw);
    cudaGetSymbolAddress((void**)&p_xroot, g_xroot);
    cudaGetSymbolAddress((void**)&p_xr, g_xr);
    cudaGetSymbolAddress((void**)&p_xh, g_xh);
    cudaGetSymbolAddress((void**)&p_ctx, g_ctx);
    cudaGetSymbolAddress((void**)&p_h1, g_h1);
    cudaGetSymbolAddress((void**)&p_ctx2, g_ctx2);

    // layer-invariant prep
    prep_eattr_kernel<<<(BS * MM * CC + 255) / 256, 256>>>(pooled, svo);
    prep_adj_kernel<<<(BS * 2 * NN + 127) / 128, 128>>>(aug, punct);
    prep_deg_kernel<<<(BS * NN + BS * MM + 127) / 128, 128>>>(s2w);

    const float* xr_in = spans;
    const float* xh_in = spans;
    for (int l = 0; l < LL; l++) {
        float* xr_out = (l == LL - 1) ? out : p_xr;
        float* xh_out = (l == LL - 1) ? out + (size_t)BS * NN * CC : p_xh;

        const float* wl = w_lin + (size_t)l * CC * HH * CC;

        // ---- HypergraphConv ----
        // xl = x_h @ w_lin  [8192,512]x[512,2048]
        sgemm(xh_in, wl, p_xl, BS * NN, HH * CC, CC, CC, HH * CC, HH * CC,
              1, 1, 0, 0, 0, 0, 0, 0);
        // el = e_attr @ w_lin  [2080,512]x[512,2048]
        sgemm(p_eattr, wl, p_el, BS * MM, HH * CC, CC, CC, HH * CC, HH * CC,
              1, 1, 0, 0, 0, 0, 0, 0);
        attdot_kernel<<<BS * NN, 128>>>(p_xl, att_x + (size_t)l * HH * CC, p_an);
        attdot_kernel<<<BS * MM, 128>>>(p_el, att_e + (size_t)l * HH * CC, p_ae);
        alpha_kernel<<<BS * NN, 128>>>(s2w);
        // msg_e[z=(b,h)] = alpha_mn[z] @ xl[b,:,h,:]   [65,256]x[256,512]
        sgemm(p_amn, p_xl, p_msge, MM, CC, NN, NN, HH * CC, CC,
              BS * HH, HH,
              (long long)HH * MM * NN, (long long)MM * NN,
              (long long)NN * HH * CC, (long long)CC,
              (long long)HH * MM * CC, (long long)MM * CC);
        scale_msge_kernel<<<(int)(((size_t)BS * HH * MM * CC + 255) / 256), 256>>>();
        // out_h_pre[z] = alpha_nm[z] @ msg_e[z]   [256,65]x[65,512]
        sgemm(p_anm, p_msge, p_ohp, NN, CC, MM, MM, CC, CC,
              BS * HH, HH,
              (long long)HH * NN * MM, (long long)NN * MM,
              (long long)HH * MM * CC, (long long)MM * CC,
              (long long)HH * NN * CC, (long long)NN * CC);
        finalize_h_kernel<<<BS * NN, CC>>>(xh_out, b_hgcn + (size_t)l * CC);

        // ---- RGCN ----
        // xw[r] = x_r @ w_rel[l,r]  (batch 2, shared A)
        sgemm(xr_in, w_rel + (size_t)l * 2 * CC * CC, p_xw, BS * NN, CC, CC, CC, CC, CC,
              2, 1, 0, 0, (long long)CC * CC, 0, (long long)BS * NN * CC, 0);
        sgemm(xr_in, w_root + (size_t)l * CC * CC, p_xroot, BS * NN, CC, CC, CC, CC, CC,
              1, 1, 0, 0, 0, 0, 0, 0);
        rgcn_kernel<<<BS * NN, CC>>>(xr_out, b_rgcn + (size_t)l * CC);

        // ---- info exchange (row 0) ----
        build_ctx_kernel<<<(BS * 2 * CC + 255) / 256, 256>>>(xr_out, xh_out);
        ie_gemm_kernel<<<dim3(2 * CC / 128, BS), 128>>>(
            p_ctx, ie_w1 + (size_t)l * 2 * CC * 2 * CC, ie_b1 + (size_t)l * 2 * CC, p_h1, 1);
        ie_gemm_kernel<<<dim3(2 * CC / 128, BS), 128>>>(
            p_h1, ie_w2 + (size_t)l * 2 * CC * 2 * CC, ie_b2 + (size_t)l * 2 * CC, p_ctx2, 0);
        writeback_kernel<<<(BS * 2 * CC + 255) / 256, 256>>>(xr_out, xh_out);

        xr_in = xr_out;
        xh_in = xh_out;
    }
    (void)in_sizes; (void)n_in; (void)out_size;
}

// round 5
// speedup vs baseline: 1.9372x; 1.9372x over previous
#include <cuda_runtime.h>
#include <cuda_bf16.h>
#include <math.h>
#include <stdint.h>

#define BS 32
#define NN 256
#define EE 64
#define CC 512
#define HH 4
#define LL 2
#define MM 65

// ---------------- scratch (static device globals; no allocation) ----------------
__device__ float g_eattr[(size_t)BS*MM*CC];              // [b,m,c]
__device__ float g_xl[(size_t)BS*NN*HH*CC];              // [b,n,h,c]
__device__ float g_el[(size_t)BS*MM*HH*CC];              // [b,m,h,c]
__device__ float g_an[BS*NN*HH];                         // [b,n,h]
__device__ float g_ae[BS*MM*HH];                         // [b,m,h]
__device__ float g_alpha_nm[(size_t)BS*HH*NN*MM];        // [b,h,n,m]
__device__ float g_alpha_mn[(size_t)BS*HH*MM*NN];        // [b,h,m,n]
__device__ float g_msge[(size_t)BS*HH*MM*CC];            // [b,h,m,c]
__device__ float g_ohp[(size_t)BS*HH*NN*CC];             // [b,h,n,c]
__device__ float g_xw[(size_t)2*BS*NN*CC];               // [r,b,n,c]
__device__ float g_xroot[(size_t)BS*NN*CC];              // [b,n,c]
__device__ float g_xr[(size_t)BS*NN*CC];
__device__ float g_xh[(size_t)BS*NN*CC];
__device__ unsigned char g_adj_idx[(size_t)BS*2*NN*NN];  // per (b,r,j): source list
__device__ int   g_adj_cnt[BS*2*NN];
__device__ float g_invdeg[BS*2*NN];
__device__ float g_invD[BS*NN];
__device__ float g_invB[BS*MM];
__device__ float g_ctx[BS*2*CC];
__device__ float g_h1[BS*2*CC];
__device__ float g_ctx2[BS*2*CC];

// ================= bf16x3 split tensor-core GEMM =================
// C = A @ B, row-major, fp32 in/out, internally A,B split into bf16 hi+lo and
// computed as Ahi*Bhi + Alo*Bhi + Ahi*Blo with fp32 accumulation (err ~1e-5).
// Tile 128x128x32, 8 warps, warp tile 64x32 via mma.m16n8k16.
// Batched via z = z1*zdiv+z2 with independent strides.

__device__ __forceinline__ void mma_bf16(float* c, const uint32_t* a, const uint32_t* b) {
    asm volatile(
        "mma.sync.aligned.m16n8k16.row.col.f32.bf16.bf16.f32 "
        "{%0,%1,%2,%3}, {%4,%5,%6,%7}, {%8,%9}, {%0,%1,%2,%3};\n"
        : "+f"(c[0]), "+f"(c[1]), "+f"(c[2]), "+f"(c[3])
        : "r"(a[0]), "r"(a[1]), "r"(a[2]), "r"(a[3]), "r"(b[0]), "r"(b[1]));
}

__device__ __forceinline__ uint32_t pack2(__nv_bfloat16 a, __nv_bfloat16 b) {
    __nv_bfloat162 t; t.x = a; t.y = b;
    uint32_t r; __builtin_memcpy(&r, &t, 4); return r;
}

__device__ __forceinline__ void split_bf(float x, __nv_bfloat16& h, __nv_bfloat16& l) {
    h = __float2bfloat16(x);
    l = __float2bfloat16(x - __bfloat162float(h));
}

#define LDK 40   // padded K stride in bf16 elems (32 data + 8 pad): conflict-free

__global__ __launch_bounds__(256, 1)
void gemm_kernel(const float* __restrict__ A, const float* __restrict__ B,
                 float* __restrict__ C,
                 int Mr, int Nc, int K, int lda, int ldb, int ldc,
                 int zdiv,
                 long long sA1, long long sA2,
                 long long sB1, long long sB2,
                 long long sC1, long long sC2)
{
    int z = blockIdx.z;
    int z1 = z / zdiv, z2 = z % zdiv;
    A += z1 * sA1 + z2 * sA2;
    B += z1 * sB1 + z2 * sB2;
    C += z1 * sC1 + z2 * sC2;

    __shared__ __nv_bfloat16 Ah_s[128 * LDK];
    __shared__ __nv_bfloat16 Al_s[128 * LDK];
    __shared__ __nv_bfloat16 Bh_s[128 * LDK];
    __shared__ __nv_bfloat16 Bl_s[128 * LDK];

    const int tid = threadIdx.x;
    const int warp = tid >> 5, lane = tid & 31;
    const int wm = warp >> 2, wn = warp & 3;     // warp grid 2x4
    const int group = lane >> 2, tg = lane & 3;
    const int rowBase = blockIdx.y * 128;
    const int colBase = blockIdx.x * 128;

    float acc[4][4][4];
    #pragma unroll
    for (int i = 0; i < 4; i++)
        #pragma unroll
        for (int j = 0; j < 4; j++)
            #pragma unroll
            for (int r = 0; r < 4; r++) acc[i][j][r] = 0.f;

    const int S = (K + 31) / 32;

    float aReg[4][4], bReg[16];
    // prologue fetch stage 0
    {
        const int k0 = 0;
        #pragma unroll
        for (int i = 0; i < 4; i++) {
            int q = i * 256 + tid, r = q >> 3, qc = q & 7;
            int gr = rowBase + r, kb = k0 + qc * 4;
            #pragma unroll
            for (int j = 0; j < 4; j++) {
                float v = 0.f; int kk = kb + j;
                if (gr < Mr && kk < K) v = A[(size_t)gr * lda + kk];
                aReg[i][j] = v;
            }
        }
        #pragma unroll
        for (int i = 0; i < 16; i++) {
            int idx = i * 256 + tid, n = idx & 127, kk = k0 + (idx >> 7);
            int gc = colBase + n; float v = 0.f;
            if (kk < K && gc < Nc) v = B[(size_t)kk * ldb + gc];
            bReg[i] = v;
        }
    }

    for (int s = 0; s < S; s++) {
        // ---- stage regs -> smem with hi/lo split ----
        #pragma unroll
        for (int i = 0; i < 4; i++) {
            int q = i * 256 + tid, r = q >> 3, qc = q & 7;
            __nv_bfloat16 h[4], l[4];
            #pragma unroll
            for (int j = 0; j < 4; j++) split_bf(aReg[i][j], h[j], l[j]);
            uint2 vh = make_uint2(pack2(h[0], h[1]), pack2(h[2], h[3]));
            uint2 vl = make_uint2(pack2(l[0], l[1]), pack2(l[2], l[3]));
            *(uint2*)(Ah_s + r * LDK + qc * 4) = vh;
            *(uint2*)(Al_s + r * LDK + qc * 4) = vl;
        }
        #pragma unroll
        for (int i = 0; i < 16; i++) {
            int idx = i * 256 + tid, n = idx & 127, k = idx >> 7;
            __nv_bfloat16 h, l;
            split_bf(bReg[i], h, l);
            Bh_s[n * LDK + k] = h;
            Bl_s[n * LDK + k] = l;
        }
        __syncthreads();

        // ---- prefetch next stage into fresh regs (overlaps with MMA) ----
        float aN[4][4], bN[16];
        if (s + 1 < S) {
            const int k0 = (s + 1) * 32;
            #pragma unroll
            for (int i = 0; i < 4; i++) {
                int q = i * 256 + tid, r = q >> 3, qc = q & 7;
                int gr = rowBase + r, kb = k0 + qc * 4;
                #pragma unroll
                for (int j = 0; j < 4; j++) {
                    float v = 0.f; int kk = kb + j;
                    if (gr < Mr && kk < K) v = A[(size_t)gr * lda + kk];
                    aN[i][j] = v;
                }
            }
            #pragma unroll
            for (int i = 0; i < 16; i++) {
                int idx = i * 256 + tid, n = idx & 127, kk = k0 + (idx >> 7);
                int gc = colBase + n; float v = 0.f;
                if (kk < K && gc < Nc) v = B[(size_t)kk * ldb + gc];
                bN[i] = v;
            }
        }

        // ---- compute: 2 k16 steps x (4 mt x 4 nt) x 3 split products ----
        #pragma unroll
        for (int ks = 0; ks < 2; ks++) {
            const int ko = ks * 16 + tg * 2;
            uint32_t Afh[4][4], Afl[4][4];
            #pragma unroll
            for (int mt = 0; mt < 4; mt++) {
                int r0 = (wm * 64 + mt * 16 + group) * LDK + ko;
                Afh[mt][0] = *(const uint32_t*)(Ah_s + r0);
                Afh[mt][1] = *(const uint32_t*)(Ah_s + r0 + 8 * LDK);
                Afh[mt][2] = *(const uint32_t*)(Ah_s + r0 + 8);
                Afh[mt][3] = *(const uint32_t*)(Ah_s + r0 + 8 * LDK + 8);
                Afl[mt][0] = *(const uint32_t*)(Al_s + r0);
                Afl[mt][1] = *(const uint32_t*)(Al_s + r0 + 8 * LDK);
                Afl[mt][2] = *(const uint32_t*)(Al_s + r0 + 8);
                Afl[mt][3] = *(const uint32_t*)(Al_s + r0 + 8 * LDK + 8);
            }
            uint32_t Bfh[4][2], Bfl[4][2];
            #pragma unroll
            for (int nt = 0; nt < 4; nt++) {
                int c0 = (wn * 32 + nt * 8 + group) * LDK + ko;
                Bfh[nt][0] = *(const uint32_t*)(Bh_s + c0);
                Bfh[nt][1] = *(const uint32_t*)(Bh_s + c0 + 8);
                Bfl[nt][0] = *(const uint32_t*)(Bl_s + c0);
                Bfl[nt][1] = *(const uint32_t*)(Bl_s + c0 + 8);
            }
            #pragma unroll
            for (int mt = 0; mt < 4; mt++)
                #pragma unroll
                for (int nt = 0; nt < 4; nt++) {
                    mma_bf16(acc[mt][nt], Afh[mt], Bfh[nt]);
                    mma_bf16(acc[mt][nt], Afl[mt], Bfh[nt]);
                    mma_bf16(acc[mt][nt], Afh[mt], Bfl[nt]);
                }
        }
        __syncthreads();

        // rotate prefetch buffers (dead values on last iter; never stored)
        #pragma unroll
        for (int i = 0; i < 4; i++)
            #pragma unroll
            for (int j = 0; j < 4; j++) aReg[i][j] = aN[i][j];
        #pragma unroll
        for (int i = 0; i < 16; i++) bReg[i] = bN[i];
    }

    // ---- epilogue ----
    #pragma unroll
    for (int mt = 0; mt < 4; mt++) {
        int r0 = rowBase + wm * 64 + mt * 16 + group;
        int r1 = r0 + 8;
        #pragma unroll
        for (int nt = 0; nt < 4; nt++) {
            int c = colBase + wn * 32 + nt * 8 + tg * 2;
            if (r0 < Mr) {
                if (c < Nc)     C[(size_t)r0 * ldc + c]     = acc[mt][nt][0];
                if (c + 1 < Nc) C[(size_t)r0 * ldc + c + 1] = acc[mt][nt][1];
            }
            if (r1 < Mr) {
                if (c < Nc)     C[(size_t)r1 * ldc + c]     = acc[mt][nt][2];
                if (c + 1 < Nc) C[(size_t)r1 * ldc + c + 1] = acc[mt][nt][3];
            }
        }
    }
}

static void sgemm(const float* A, const float* B, float* C,
                  int Mr, int Nc, int K, int lda, int ldb, int ldc,
                  int batch, int zdiv,
                  long long sA1, long long sA2, long long sB1, long long sB2,
                  long long sC1, long long sC2)
{
    dim3 grid((Nc + 127) / 128, (Mr + 127) / 128, batch);
    gemm_kernel<<<grid, 256>>>(A, B, C, Mr, Nc, K, lda, ldb, ldc,
                               zdiv, sA1, sA2, sB1, sB2, sC1, sC2);
}

// ---------------- prep kernels (layer-invariant) ----------------
__global__ void prep_eattr_kernel(const float* __restrict__ pooled,
                                  const float* __restrict__ svo) {
    int idx = blockIdx.x * blockDim.x + threadIdx.x;
    if (idx >= BS * MM * CC) return;
    int c = idx % CC;
    int bm = idx / CC;
    int m = bm % MM, b = bm / MM;
    g_eattr[idx] = (m == 0) ? pooled[b * CC + c]
                            : svo[((size_t)(b * EE + (m - 1))) * CC + c];
}

__global__ void prep_adj_kernel(const int* __restrict__ aug,
                                const int* __restrict__ punct) {
    int idx = blockIdx.x * blockDim.x + threadIdx.x;   // (b*2+r)*NN + j
    if (idx >= BS * 2 * NN) return;
    int j = idx % NN;
    int br = idx / NN;
    int r = br & 1, b = br >> 1;
    unsigned char* lst = g_adj_idx + (size_t)idx * NN;
    int cnt = 0;
    for (int i = 0; i < NN; i++) {
        int a = aug[((size_t)(b * NN + i)) * NN + j];
        int v = (r == 1) ? a : (punct[((size_t)(b * NN + i)) * NN + j] * (1 - a));
        if (v) lst[cnt++] = (unsigned char)i;
    }
    g_adj_cnt[idx] = cnt;
    g_invdeg[idx] = (cnt > 0) ? 1.f / (float)cnt : 0.f;
}

__global__ void prep_deg_kernel(const int* __restrict__ s2w) {
    int idx = blockIdx.x * blockDim.x + threadIdx.x;
    if (idx < BS * NN) {
        const int* row = s2w + (size_t)idx * EE;
        int s = 1;                               // global hyperedge
        for (int e = 0; e < EE; e++) s += row[e];
        g_invD[idx] = 1.f / (float)s;            // s >= 1 always
    } else if (idx < BS * NN + BS * MM) {
        int t = idx - BS * NN;
        int m = t % MM, b = t / MM;
        if (m == 0) {
            g_invB[t] = 1.f / (float)NN;
        } else {
            int s = 0;
            for (int n = 0; n < NN; n++) s += s2w[((size_t)(b * NN + n)) * EE + (m - 1)];
            g_invB[t] = (s > 0) ? 1.f / (float)s : 0.f;
        }
    }
}

// ---------------- attention path ----------------
__global__ void attdot_kernel(const float* __restrict__ X,
                              const float* __restrict__ att,
                              float* __restrict__ out) {
    int row = blockIdx.x;
    int h = threadIdx.x >> 5, lane = threadIdx.x & 31;
    const float* x = X + ((size_t)row * HH + h) * CC;
    const float* a = att + h * CC;
    float acc = 0.f;
    for (int c = lane; c < CC; c += 32) acc += x[c] * a[c];
    #pragma unroll
    for (int o = 16; o; o >>= 1) acc += __shfl_xor_sync(0xffffffffu, acc, o);
    if (lane == 0) out[row * HH + h] = acc;
}

__global__ void alpha_kernel(const int* __restrict__ s2w) {
    int bn = blockIdx.x;
    int b = bn >> 8, n = bn & 255;
    int h = threadIdx.x >> 5, lane = threadIdx.x & 31;
    float anv = g_an[bn * HH + h];
    float v[3]; int ok[3];
    #pragma unroll
    for (int s = 0; s < 3; s++) {
        int m = lane + s * 32;
        float vv = -1e30f; int o = 0;
        if (m < MM) {
            o = (m == 0) || (s2w[(size_t)bn * EE + (m - 1)] != 0);
            if (o) {
                float x = anv + g_ae[(b * MM + m) * HH + h];
                vv = (x > 0.f) ? x : 0.2f * x;   // leaky_relu 0.2
            }
        }
        v[s] = vv; ok[s] = o;
    }
    float mx = fmaxf(v[0], fmaxf(v[1], v[2]));
    #pragma unroll
    for (int o = 16; o; o >>= 1) mx = fmaxf(mx, __shfl_xor_sync(0xffffffffu, mx, o));
    float e[3]; float sum = 0.f;
    #pragma unroll
    for (int s = 0; s < 3; s++) { e[s] = ok[s] ? expf(v[s] - mx) : 0.f; sum += e[s]; }
    #pragma unroll
    for (int o = 16; o; o >>= 1) sum += __shfl_xor_sync(0xffffffffu, sum, o);
    float inv = 1.f / sum;
    size_t z = (size_t)(b * HH + h);
    #pragma unroll
    for (int s = 0; s < 3; s++) {
        int m = lane + s * 32;
        if (m < MM) {
            float a = e[s] * inv;
            g_alpha_nm[(z * NN + n) * MM + m] = a;
            g_alpha_mn[(z * MM + m) * NN + n] = a;
        }
    }
}

__global__ void scale_msge_kernel() {
    size_t idx = (size_t)blockIdx.x * blockDim.x + threadIdx.x;
    if (idx >= (size_t)BS * HH * MM * CC) return;
    int m = (int)((idx / CC) % MM);
    int b = (int)(idx / ((size_t)HH * MM * CC));
    g_msge[idx] *= g_invB[b * MM + m];
}

__global__ void finalize_h_kernel(float* __restrict__ out, const float* __restrict__ bias) {
    int bn = blockIdx.x; int c = threadIdx.x;
    int b = bn >> 8, n = bn & 255;
    float s = 0.f;
    #pragma unroll
    for (int h = 0; h < HH; h++)
        s += g_ohp[(((size_t)(b * HH + h)) * NN + n) * CC + c];
    float v = s * 0.25f * g_invD[bn] + bias[c];
    out[(size_t)bn * CC + c] = (v > 0.f) ? v : 0.f;
}

// ---------------- RGCN combine ----------------
__global__ void rgcn_kernel(float* __restrict__ out, const float* __restrict__ bias) {
    int bj = blockIdx.x; int c = threadIdx.x;
    int b = bj >> 8, j = bj & 255;
    float acc = g_xroot[(size_t)bj * CC + c];
    #pragma unroll
    for (int r = 0; r < 2; r++) {
        int e = (b * 2 + r) * NN + j;
        int cnt = g_adj_cnt[e];
        const unsigned char* lst = g_adj_idx + (size_t)e * NN;
        float p = 0.f;
        for (int t = 0; t < cnt; t++) {
            int i = lst[t];
            p += g_xw[(size_t)r * BS * NN * CC + ((size_t)(b * NN + i)) * CC + c];
        }
        acc += p * g_invdeg[e];
    }
    acc += bias[c];
    out[(size_t)bj * CC + c] = (acc > 0.f) ? acc : 0.f;
}

// ---------------- info exchange ----------------
__global__ void build_ctx_kernel(const float* __restrict__ xr, const float* __restrict__ xh) {
    int idx = blockIdx.x * blockDim.x + threadIdx.x;
    if (idx >= BS * 2 * CC) return;
    int c = idx % (2 * CC); int b = idx / (2 * CC);
    g_ctx[idx] = (c < CC) ? xr[(size_t)b * NN * CC + c]
                          : xh[(size_t)b * NN * CC + (c - CC)];
}

__global__ void ie_gemm_kernel(const float* __restrict__ in, const float* __restrict__ W,
                               const float* __restrict__ bias, float* __restrict__ out,
                               int relu) {
    __shared__ float s_in[2 * CC];
    int b = blockIdx.y;
    int j = blockIdx.x * 128 + threadIdx.x;
    for (int t = threadIdx.x; t < 2 * CC; t += 128) s_in[t] = in[b * 2 * CC + t];
    __syncthreads();
    float a0 = 0.f, a1 = 0.f, a2 = 0.f, a3 = 0.f;
    for (int k = 0; k < 2 * CC; k += 4) {
        a0 += s_in[k + 0] * W[(size_t)(k + 0) * (2 * CC) + j];
        a1 += s_in[k + 1] * W[(size_t)(k + 1) * (2 * CC) + j];
        a2 += s_in[k + 2] * W[(size_t)(k + 2) * (2 * CC) + j];
        a3 += s_in[k + 3] * W[(size_t)(k + 3) * (2 * CC) + j];
    }
    float acc = (a0 + a1) + (a2 + a3) + bias[j];
    if (relu) acc = (acc > 0.f) ? acc : 0.f;
    out[b * 2 * CC + j] = acc;
}

__global__ void writeback_kernel(float* __restrict__ xr, float* __restrict__ xh) {
    int idx = blockIdx.x * blockDim.x + threadIdx.x;
    if (idx >= BS * 2 * CC) return;
    int c = idx % (2 * CC); int b = idx / (2 * CC);
    float v = g_ctx2[idx];
    if (c < CC) xr[(size_t)b * NN * CC + c] = v;
    else        xh[(size_t)b * NN * CC + (c - CC)] = v;
}

// ---------------- launch ----------------
extern "C" void kernel_launch(void* const* d_in, const int* in_sizes, int n_in,
                              void* d_out, int out_size) {
    const float* spans  = (const float*)d_in[0];
    const float* svo    = (const float*)d_in[1];
    const float* pooled = (const float*)d_in[2];
    const int*   s2w    = (const int*)d_in[3];
    const int*   aug    = (const int*)d_in[4];
    const int*   punct  = (const int*)d_in[5];
    const float* w_rel  = (const float*)d_in[6];
    const float* w_root = (const float*)d_in[7];
    const float* b_rgcn = (const float*)d_in[8];
    const float* w_lin  = (const float*)d_in[9];
    const float* att_x  = (const float*)d_in[10];
    const float* att_e  = (const float*)d_in[11];
    const float* b_hgcn = (const float*)d_in[12];
    const float* ie_w1  = (const float*)d_in[13];
    const float* ie_b1  = (const float*)d_in[14];
    const float* ie_w2  = (const float*)d_in[15];
    const float* ie_b2  = (const float*)d_in[16];
    float* out = (float*)d_out;

    float *p_eattr, *p_xl, *p_el, *p_an, *p_ae, *p_anm, *p_amn, *p_msge, *p_ohp;
    float *p_xw, *p_xroot, *p_xr, *p_xh, *p_ctx, *p_h1, *p_ctx2;
    cudaGetSymbolAddress((void**)&p_eattr, g_eattr);
    cudaGetSymbolAddress((void**)&p_xl, g_xl);
    cudaGetSymbolAddress((void**)&p_el, g_el);
    cudaGetSymbolAddress((void**)&p_an, g_an);
    cudaGetSymbolAddress((void**)&p_ae, g_ae);
    cudaGetSymbolAddress((void**)&p_anm, g_alpha_nm);
    cudaGetSymbolAddress((void**)&p_amn, g_alpha_mn);
    cudaGetSymbolAddress((void**)&p_msge, g_msge);
    cudaGetSymbolAddress((void**)&p_ohp, g_ohp);
    cudaGetSymbolAddress((void**)&p_xw, g_xw);
    cudaGetSymbolAddress((void**)&p_xroot, g_xroot);
    cudaGetSymbolAddress((void**)&p_xr, g_xr);
    cudaGetSymbolAddress((void**)&p_xh, g_xh);
    cudaGetSymbolAddress((void**)&p_ctx, g_ctx);
    cudaGetSymbolAddress((void**)&p_h1, g_h1);
    cudaGetSymbolAddress((void**)&p_ctx2, g_ctx2);

    // layer-invariant prep
    prep_eattr_kernel<<<(BS * MM * CC + 255) / 256, 256>>>(pooled, svo);
    prep_adj_kernel<<<(BS * 2 * NN + 127) / 128, 128>>>(aug, punct);
    prep_deg_kernel<<<(BS * NN + BS * MM + 127) / 128, 128>>>(s2w);

    const float* xr_in = spans;
    const float* xh_in = spans;
    for (int l = 0; l < LL; l++) {
        float* xr_out = (l == LL - 1) ? out : p_xr;
        float* xh_out = (l == LL - 1) ? out + (size_t)BS * NN * CC : p_xh;

        const float* wl = w_lin + (size_t)l * CC * HH * CC;

        // ---- HypergraphConv ----
        // xl = x_h @ w_lin  [8192,512]x[512,2048]
        sgemm(xh_in, wl, p_xl, BS * NN, HH * CC, CC, CC, HH * CC, HH * CC,
              1, 1, 0, 0, 0, 0, 0, 0);
        // el = e_attr @ w_lin  [2080,512]x[512,2048]
        sgemm(p_eattr, wl, p_el, BS * MM, HH * CC, CC, CC, HH * CC, HH * CC,
              1, 1, 0, 0, 0, 0, 0, 0);
        attdot_kernel<<<BS * NN, 128>>>(p_xl, att_x + (size_t)l * HH * CC, p_an);
        attdot_kernel<<<BS * MM, 128>>>(p_el, att_e + (size_t)l * HH * CC, p_ae);
        alpha_kernel<<<BS * NN, 128>>>(s2w);
        // msg_e[z=(b,h)] = alpha_mn[z] @ xl[b,:,h,:]   [65,256]x[256,512]
        sgemm(p_amn, p_xl, p_msge, MM, CC, NN, NN, HH * CC, CC,
              BS * HH, HH,
              (long long)HH * MM * NN, (long long)MM * NN,
              (long long)NN * HH * CC, (long long)CC,
              (long long)HH * MM * CC, (long long)MM * CC);
        scale_msge_kernel<<<(int)(((size_t)BS * HH * MM * CC + 255) / 256), 256>>>();
        // out_h_pre[z] = alpha_nm[z] @ msg_e[z]   [256,65]x[65,512]
        sgemm(p_anm, p_msge, p_ohp, NN, CC, MM, MM, CC, CC,
              BS * HH, HH,
              (long long)HH * NN * MM, (long long)NN * MM,
              (long long)HH * MM * CC, (long long)MM * CC,
              (long long)HH * NN * CC, (long long)NN * CC);
        finalize_h_kernel<<<BS * NN, CC>>>(xh_out, b_hgcn + (size_t)l * CC);

        // ---- RGCN ----
        sgemm(xr_in, w_rel + (size_t)l * 2 * CC * CC, p_xw, BS * NN, CC, CC, CC, CC, CC,
              2, 1, 0, 0, (long long)CC * CC, 0, (long long)BS * NN * CC, 0);
        sgemm(xr_in, w_root + (size_t)l * CC * CC, p_xroot, BS * NN, CC, CC, CC, CC, CC,
              1, 1, 0, 0, 0, 0, 0, 0);
        rgcn_kernel<<<BS * NN, CC>>>(xr_out, b_rgcn + (size_t)l * CC);

        // ---- info exchange (row 0) ----
        build_ctx_kernel<<<(BS * 2 * CC + 255) / 256, 256>>>(xr_out, xh_out);
        ie_gemm_kernel<<<dim3(2 * CC / 128, BS), 128>>>(
            p_ctx, ie_w1 + (size_t)l * 2 * CC * 2 * CC, ie_b1 + (size_t)l * 2 * CC, p_h1, 1);
        ie_gemm_kernel<<<dim3(2 * CC / 128, BS), 128>>>(
            p_h1, ie_w2 + (size_t)l * 2 * CC * 2 * CC, ie_b2 + (size_t)l * 2 * CC, p_ctx2, 0);
        writeback_kernel<<<(BS * 2 * CC + 255) / 256, 256>>>(xr_out, xh_out);

        xr_in = xr_out;
        xh_in = xh_out;
    }
    (void)in_sizes; (void)n_in; (void)out_size;
}

// round 6
// speedup vs baseline: 2.6941x; 1.3907x over previous
#include <cuda_runtime.h>
#include <cuda_bf16.h>
#include <math.h>
#include <stdint.h>

#define BS 32
#define NN 256
#define EE 64
#define CC 512
#define HH 4
#define LL 2
#define MM 65
#define ALD 80   // padded lda for alpha_nm (160B rows, 16B aligned)

typedef __nv_bfloat16 bf16;

// ---------------- fp32 scratch ----------------
__device__ float g_ohp[(size_t)BS*HH*NN*CC];
__device__ float g_agg[(size_t)2*BS*NN*CC];
__device__ float g_xroot[(size_t)BS*NN*CC];
__device__ float g_xr[(size_t)BS*NN*CC];
__device__ float g_xh[(size_t)BS*NN*CC];
__device__ float g_an[BS*NN*HH];
__device__ float g_ae[BS*MM*HH];
__device__ float g_invD[BS*NN];
__device__ float g_invB[BS*MM];
__device__ float g_ctx[BS*2*CC];
__device__ float g_h1[BS*2*CC];
__device__ float g_ctx2[BS*2*CC];

// ---------------- bf16 hi/lo planes ----------------
__device__ bf16 g_x0h[(size_t)BS*NN*CC],      g_x0l[(size_t)BS*NN*CC];
__device__ bf16 g_eah[(size_t)BS*MM*CC],      g_eal[(size_t)BS*MM*CC];
__device__ bf16 g_wlh[(size_t)LL*CC*HH*CC],   g_wll[(size_t)LL*CC*HH*CC];
__device__ bf16 g_wrh[(size_t)LL*2*CC*CC],    g_wrl[(size_t)LL*2*CC*CC];
__device__ bf16 g_wth[(size_t)LL*CC*CC],      g_wtl[(size_t)LL*CC*CC];
__device__ bf16 g_xlh[(size_t)BS*NN*HH*CC],   g_xll[(size_t)BS*NN*HH*CC];
__device__ bf16 g_elh[(size_t)BS*MM*HH*CC],   g_ell[(size_t)BS*MM*HH*CC];
__device__ bf16 g_amnh[(size_t)BS*HH*MM*NN],  g_amnl[(size_t)BS*HH*MM*NN];
__device__ bf16 g_anmh[(size_t)BS*HH*NN*ALD], g_anml[(size_t)BS*HH*NN*ALD];
__device__ bf16 g_msgh[(size_t)BS*HH*MM*CC],  g_msgl[(size_t)BS*HH*MM*CC];
__device__ bf16 g_xwh[(size_t)2*BS*NN*CC],    g_xwl[(size_t)2*BS*NN*CC];
__device__ bf16 g_Anh[(size_t)2*BS*NN*NN],    g_Anl[(size_t)2*BS*NN*NN];
__device__ bf16 g_xrh[(size_t)BS*NN*CC],      g_xrl[(size_t)BS*NN*CC];
__device__ bf16 g_xhh[(size_t)BS*NN*CC],      g_xhl[(size_t)BS*NN*CC];

// ---------------- helpers ----------------
__device__ __forceinline__ void split_bf(float x, bf16& h, bf16& l) {
    h = __float2bfloat16(x);
    l = __float2bfloat16(x - __bfloat162float(h));
}
__device__ __forceinline__ uint32_t pack_split_hi(float a, float b, uint32_t& lo_out) {
    bf16 h0, l0, h1, l1;
    split_bf(a, h0, l0); split_bf(b, h1, l1);
    __nv_bfloat162 hp; hp.x = h0; hp.y = h1;
    __nv_bfloat162 lp; lp.x = l0; lp.y = l1;
    uint32_t hv, lv;
    __builtin_memcpy(&hv, &hp, 4); __builtin_memcpy(&lv, &lp, 4);
    lo_out = lv; return hv;
}
__device__ __forceinline__ void mma_bf16(float* c, const uint32_t* a, const uint32_t* b) {
    asm volatile(
        "mma.sync.aligned.m16n8k16.row.col.f32.bf16.bf16.f32 "
        "{%0,%1,%2,%3}, {%4,%5,%6,%7}, {%8,%9}, {%0,%1,%2,%3};\n"
        : "+f"(c[0]), "+f"(c[1]), "+f"(c[2]), "+f"(c[3])
        : "r"(a[0]), "r"(a[1]), "r"(a[2]), "r"(a[3]), "r"(b[0]), "r"(b[1]));
}
__device__ __forceinline__ void cp16(uint32_t dst, const void* src, int sz) {
    asm volatile("cp.async.cg.shared.global [%0], [%1], 16, %2;\n"
                 :: "r"(dst), "l"(src), "r"(sz));
}
#define LDSM4(d0,d1,d2,d3,a) \
    asm volatile("ldmatrix.sync.aligned.m8n8.x4.shared.b16 {%0,%1,%2,%3}, [%4];" \
                 : "=r"(d0),"=r"(d1),"=r"(d2),"=r"(d3) : "r"(a))
#define LDSM4T(d0,d1,d2,d3,a) \
    asm volatile("ldmatrix.sync.aligned.m8n8.x4.trans.shared.b16 {%0,%1,%2,%3}, [%4];" \
                 : "=r"(d0),"=r"(d1),"=r"(d2),"=r"(d3) : "r"(a))

// ================= split-bf16 tensor-core GEMM (cp.async pipeline) =================
// C = (Ah+Al) @ (Bh+Bl) via AhBh + AhBl + AlBh, fp32 accum.
// Tile 128x128x32, 256 threads, 8 warps (2x4), warp tile 64x32, mma m16n8k16.
// Double-buffered cp.async, ldmatrix fragment loads, XOR-swizzled smem.
// Outputs: optional fp32 C and/or bf16 hi/lo planes (same strides).
#define STG_BYTES 32768   // per stage: Ah 8K | Al 8K | Bh 8K | Bl 8K

__global__ __launch_bounds__(256, 2)
void gemm_kernel(const bf16* __restrict__ Ah, const bf16* __restrict__ Al,
                 const bf16* __restrict__ Bh, const bf16* __restrict__ Bl,
                 float* __restrict__ Cf, bf16* __restrict__ Chp, bf16* __restrict__ Clp,
                 int Mr, int Nc, int K, int lda, int ldb, int ldc,
                 int zdiv,
                 long long sA1, long long sA2,
                 long long sB1, long long sB2,
                 long long sC1, long long sC2)
{
    extern __shared__ __align__(128) unsigned char smem_raw[];
    uint32_t smem = (uint32_t)__cvta_generic_to_shared(smem_raw);

    int z = blockIdx.z;
    int z1 = z / zdiv, z2 = z % zdiv;
    long long offA = z1 * sA1 + z2 * sA2;
    long long offB = z1 * sB1 + z2 * sB2;
    long long offC = z1 * sC1 + z2 * sC2;
    Ah += offA; Al += offA; Bh += offB; Bl += offB;

    const int tid = threadIdx.x;
    const int warp = tid >> 5, lane = tid & 31;
    const int wm = warp >> 2, wn = warp & 3;
    const int g = lane >> 2, tg = lane & 3;
    const int rowBase = blockIdx.y * 128;
    const int colBase = blockIdx.x * 128;

    // ---- cp.async source/dest geometry (2 A-chunks + 2 B-chunks per thread/plane) ----
    int am[2], ac[2], adst[2];
    int bk[2], bc[2], bdst[2];
    #pragma unroll
    for (int i = 0; i < 2; i++) {
        int q = i * 256 + tid;
        am[i] = q >> 2; ac[i] = q & 3;
        adst[i] = am[i] * 64 + ((ac[i] ^ (am[i] & 3)) << 4);
        bk[i] = q >> 4; bc[i] = q & 15;
        bdst[i] = bk[i] * 256 + ((bc[i] ^ (bk[i] & 7)) << 4);
    }

    // ---- ldmatrix lane addresses ----
    int mloc = wm * 64 + (lane & 15);
    int addrA0 = mloc * 64 + (((lane >> 4) ^ (mloc & 3)) << 4);
    int kB = lane & 15;
    int cB0 = wn * 4 + (lane >> 4);
    int addrB0 = kB * 256 + ((cB0 ^ (kB & 7)) << 4);

    float acc[4][4][4];
    #pragma unroll
    for (int i = 0; i < 4; i++)
        #pragma unroll
        for (int j = 0; j < 4; j++)
            #pragma unroll
            for (int r = 0; r < 4; r++) acc[i][j][r] = 0.f;

    const int S = (K + 31) / 32;

    // ---- stage copier ----
    auto copy_stage = [&](int s, int buf) {
        int k0 = s * 32;
        uint32_t base = smem + buf * STG_BYTES;
        #pragma unroll
        for (int i = 0; i < 2; i++) {
            int gr = rowBase + am[i];
            int kk = k0 + ac[i] * 8;
            int rem = (gr < Mr) ? (K - kk) * 2 : 0;
            int sz = rem < 0 ? 0 : (rem > 16 ? 16 : rem);
            int grc = (gr < Mr) ? gr : 0;
            int kkc = (sz > 0) ? kk : 0;
            size_t so = (size_t)grc * lda + kkc;
            cp16(base + adst[i],        Ah + so, sz);
            cp16(base + 8192 + adst[i], Al + so, sz);
        }
        #pragma unroll
        for (int i = 0; i < 2; i++) {
            int kk = k0 + bk[i];
            int gc = colBase + bc[i] * 8;
            int ok = (kk < K) && (gc < Nc);
            int kkc = ok ? kk : 0;
            int gcc = ok ? gc : 0;
            size_t so = (size_t)kkc * ldb + gcc;
            cp16(base + 16384 + bdst[i], Bh + so, ok ? 16 : 0);
            cp16(base + 24576 + bdst[i], Bl + so, ok ? 16 : 0);
        }
    };

    copy_stage(0, 0);
    asm volatile("cp.async.commit_group;\n");

    for (int s = 0; s < S; s++) {
        if (s + 1 < S) copy_stage(s + 1, (s + 1) & 1);
        asm volatile("cp.async.commit_group;\n");
        asm volatile("cp.async.wait_group 1;\n");
        __syncthreads();

        uint32_t aH = smem + (s & 1) * STG_BYTES;
        uint32_t aL = aH + 8192;
        uint32_t bH = aH + 16384;
        uint32_t bL = aH + 24576;

        #pragma unroll
        for (int ks = 0; ks < 2; ks++) {
            int axor = ks * 32;
            int bofs = ks * 4096;
            uint32_t Afh[4][4], Bfh[4][2];
            #pragma unroll
            for (int mt = 0; mt < 4; mt++)
                LDSM4(Afh[mt][0], Afh[mt][1], Afh[mt][2], Afh[mt][3],
                      aH + (uint32_t)(((addrA0 + mt * 1024) ^ axor)));
            #pragma unroll
            for (int u = 0; u < 2; u++) {
                uint32_t d0, d1, d2, d3;
                LDSM4T(d0, d1, d2, d3, bH + (uint32_t)(((addrB0 ^ (u * 32)) + bofs)));
                Bfh[2*u][0] = d0; Bfh[2*u][1] = d1;
                Bfh[2*u+1][0] = d2; Bfh[2*u+1][1] = d3;
            }
            #pragma unroll
            for (int mt = 0; mt < 4; mt++)
                #pragma unroll
                for (int nt = 0; nt < 4; nt++)
                    mma_bf16(acc[mt][nt], Afh[mt], Bfh[nt]);

            // hi * lo(B)
            #pragma unroll
            for (int u = 0; u < 2; u++) {
                uint32_t d0, d1, d2, d3;
                LDSM4T(d0, d1, d2, d3, bL + (uint32_t)(((addrB0 ^ (u * 32)) + bofs)));
                uint32_t Bfl0[2] = {d0, d1}, Bfl1[2] = {d2, d3};
                #pragma unroll
                for (int mt = 0; mt < 4; mt++) {
                    mma_bf16(acc[mt][2*u],   Afh[mt], Bfl0);
                    mma_bf16(acc[mt][2*u+1], Afh[mt], Bfl1);
                }
            }
            // lo(A) * hi
            #pragma unroll
            for (int mt = 0; mt < 4; mt++) {
                uint32_t Afl[4];
                LDSM4(Afl[0], Afl[1], Afl[2], Afl[3],
                      aL + (uint32_t)(((addrA0 + mt * 1024) ^ axor)));
                #pragma unroll
                for (int nt = 0; nt < 4; nt++)
                    mma_bf16(acc[mt][nt], Afl, Bfh[nt]);
            }
        }
        __syncthreads();
    }

    // ---- epilogue ----
    float* Cw = Cf ? (Cf + offC) : nullptr;
    bf16* Chw = Chp ? (Chp + offC) : nullptr;
    bf16* Clw = Clp ? (Clp + offC) : nullptr;
    #pragma unroll
    for (int mt = 0; mt < 4; mt++) {
        int r0 = rowBase + wm * 64 + mt * 16 + g;
        #pragma unroll
        for (int half = 0; half < 2; half++) {
            int r = r0 + half * 8;
            if (r >= Mr) continue;
            #pragma unroll
            for (int nt = 0; nt < 4; nt++) {
                int c = colBase + wn * 32 + nt * 8 + tg * 2;
                if (c >= Nc) continue;
                float v0 = acc[mt][nt][half * 2];
                float v1 = acc[mt][nt][half * 2 + 1];
                size_t o = (size_t)r * ldc + c;
                if (Cw) { Cw[o] = v0; Cw[o + 1] = v1; }
                if (Chw) {
                    uint32_t lv, hv = pack_split_hi(v0, v1, lv);
                    *(uint32_t*)(Chw + o) = hv;
                    *(uint32_t*)(Clw + o) = lv;
                }
            }
        }
    }
}

static void gemm(const bf16* Ah, const bf16* Al, const bf16* Bh, const bf16* Bl,
                 float* Cf, bf16* Chp, bf16* Clp,
                 int Mr, int Nc, int K, int lda, int ldb, int ldc,
                 int batch, int zdiv,
                 long long sA1, long long sA2, long long sB1, long long sB2,
                 long long sC1, long long sC2)
{
    dim3 grid((Nc + 127) / 128, (Mr + 127) / 128, batch);
    gemm_kernel<<<grid, 256, 2 * STG_BYTES>>>(Ah, Al, Bh, Bl, Cf, Chp, Clp,
        Mr, Nc, K, lda, ldb, ldc, zdiv, sA1, sA2, sB1, sB2, sC1, sC2);
}

// ---------------- prep kernels ----------------
__global__ void split_kernel(const float* __restrict__ in, bf16* __restrict__ hi,
                             bf16* __restrict__ lo, size_t n) {
    size_t i = (size_t)blockIdx.x * blockDim.x + threadIdx.x;
    if (i >= n) return;
    bf16 h, l; split_bf(in[i], h, l);
    hi[i] = h; lo[i] = l;
}

__global__ void prep_eattr_kernel(const float* __restrict__ pooled,
                                  const float* __restrict__ svo) {
    int idx = blockIdx.x * blockDim.x + threadIdx.x;
    if (idx >= BS * MM * CC) return;
    int c = idx % CC;
    int bm = idx / CC;
    int m = bm % MM, b = bm / MM;
    float v = (m == 0) ? pooled[b * CC + c]
                       : svo[((size_t)(b * EE + (m - 1))) * CC + c];
    bf16 h, l; split_bf(v, h, l);
    g_eah[idx] = h; g_eal[idx] = l;
}

__global__ void prep_deg_kernel(const int* __restrict__ s2w) {
    int idx = blockIdx.x * blockDim.x + threadIdx.x;
    if (idx < BS * NN) {
        const int* row = s2w + (size_t)idx * EE;
        int s = 1;
        for (int e = 0; e < EE; e++) s += row[e];
        g_invD[idx] = 1.f / (float)s;
    } else if (idx < BS * NN + BS * MM) {
        int t = idx - BS * NN;
        int m = t % MM, b = t / MM;
        if (m == 0) g_invB[t] = 1.f / (float)NN;
        else {
            int s = 0;
            for (int n = 0; n < NN; n++) s += s2w[((size_t)(b * NN + n)) * EE + (m - 1)];
            g_invB[t] = (s > 0) ? 1.f / (float)s : 0.f;
        }
    }
}

// normalized adjacency: Anorm[r][b][j][i] = rel(i,j) * invdeg(r,b,j), split planes
__global__ void prep_anorm_kernel(const int* __restrict__ aug,
                                  const int* __restrict__ punct) {
    int t = blockIdx.x * blockDim.x + threadIdx.x;
    if (t >= 2 * BS * NN) return;
    int j = t % NN;
    int b = (t / NN) % BS;
    int r = t / (NN * BS);
    int cnt = 0;
    for (int i = 0; i < NN; i++) {
        int a = aug[((size_t)(b * NN + i)) * NN + j];
        int v = r ? a : (punct[((size_t)(b * NN + i)) * NN + j] * (1 - a));
        cnt += v;
    }
    float val = cnt ? 1.f / (float)cnt : 0.f;
    bf16 vh, vl; split_bf(val, vh, vl);
    size_t base = ((size_t)(r * BS + b) * NN + j) * NN;
    for (int i = 0; i < NN; i++) {
        int a = aug[((size_t)(b * NN + i)) * NN + j];
        int v = r ? a : (punct[((size_t)(b * NN + i)) * NN + j] * (1 - a));
        g_Anh[base + i] = v ? vh : (bf16)__float2bfloat16(0.f);
        g_Anl[base + i] = v ? vl : (bf16)__float2bfloat16(0.f);
    }
}

// ---------------- attention path ----------------
__global__ void attdot_kernel(const bf16* __restrict__ Xh, const bf16* __restrict__ Xl,
                              const float* __restrict__ att, float* __restrict__ out) {
    int row = blockIdx.x;
    int h = threadIdx.x >> 5, lane = threadIdx.x & 31;
    const bf16* xh = Xh + ((size_t)row * HH + h) * CC;
    const bf16* xl = Xl + ((size_t)row * HH + h) * CC;
    const float* a = att + h * CC;
    float acc = 0.f;
    for (int c = lane; c < CC; c += 32)
        acc += (__bfloat162float(xh[c]) + __bfloat162float(xl[c])) * a[c];
    #pragma unroll
    for (int o = 16; o; o >>= 1) acc += __shfl_xor_sync(0xffffffffu, acc, o);
    if (lane == 0) out[row * HH + h] = acc;
}

// masked softmax; writes alpha_mn planes and invB-scaled alpha_nm planes
__global__ void alpha_kernel(const int* __restrict__ s2w) {
    int bn = blockIdx.x;
    int b = bn >> 8, n = bn & 255;
    int h = threadIdx.x >> 5, lane = threadIdx.x & 31;
    float anv = g_an[bn * HH + h];
    float v[3]; int ok[3];
    #pragma unroll
    for (int s = 0; s < 3; s++) {
        int m = lane + s * 32;
        float vv = -1e30f; int o = 0;
        if (m < MM) {
            o = (m == 0) || (s2w[(size_t)bn * EE + (m - 1)] != 0);
            if (o) {
                float x = anv + g_ae[(b * MM + m) * HH + h];
                vv = (x > 0.f) ? x : 0.2f * x;
            }
        }
        v[s] = vv; ok[s] = o;
    }
    float mx = fmaxf(v[0], fmaxf(v[1], v[2]));
    #pragma unroll
    for (int o = 16; o; o >>= 1) mx = fmaxf(mx, __shfl_xor_sync(0xffffffffu, mx, o));
    float e[3]; float sum = 0.f;
    #pragma unroll
    for (int s = 0; s < 3; s++) { e[s] = ok[s] ? expf(v[s] - mx) : 0.f; sum += e[s]; }
    #pragma unroll
    for (int o = 16; o; o >>= 1) sum += __shfl_xor_sync(0xffffffffu, sum, o);
    float inv = 1.f / sum;
    size_t z = (size_t)(b * HH + h);
    #pragma unroll
    for (int s = 0; s < 3; s++) {
        int m = lane + s * 32;
        if (m < MM) {
            float a = e[s] * inv;
            bf16 hb, lb;
            split_bf(a, hb, lb);
            size_t o1 = (z * MM + m) * NN + n;
            g_amnh[o1] = hb; g_amnl[o1] = lb;
            float as = a * g_invB[b * MM + m];
            split_bf(as, hb, lb);
            size_t o2 = (z * NN + n) * ALD + m;
            g_anmh[o2] = hb; g_anml[o2] = lb;
        }
    }
}

// head mean + invD + bias + relu -> xh_out fp32 + split planes
__global__ void finalize_h_kernel(float* __restrict__ out, const float* __restrict__ bias) {
    int bn = blockIdx.x; int c = threadIdx.x;
    int b = bn >> 8, n = bn & 255;
    float s = 0.f;
    #pragma unroll
    for (int h = 0; h < HH; h++)
        s += g_ohp[(((size_t)(b * HH + h)) * NN + n) * CC + c];
    float v = s * 0.25f * g_invD[bn] + bias[c];
    v = (v > 0.f) ? v : 0.f;
    size_t o = (size_t)bn * CC + c;
    out[o] = v;
    bf16 hb, lb; split_bf(v, hb, lb);
    g_xhh[o] = hb; g_xhl[o] = lb;
}

// agg0 + agg1 + xroot + bias, relu -> xr_out fp32 + split planes
__global__ void combine_rgcn_kernel(float* __restrict__ out, const float* __restrict__ bias) {
    int bj = blockIdx.x; int c = threadIdx.x;
    size_t o = (size_t)bj * CC + c;
    float v = g_agg[o] + g_agg[(size_t)BS * NN * CC + o] + g_xroot[o] + bias[c];
    v = (v > 0.f) ? v : 0.f;
    out[o] = v;
    bf16 hb, lb; split_bf(v, hb, lb);
    g_xrh[o] = hb; g_xrl[o] = lb;
}

// ---------------- info exchange ----------------
__global__ void build_ctx_kernel(const float* __restrict__ xr, const float* __restrict__ xh) {
    int idx = blockIdx.x * blockDim.x + threadIdx.x;
    if (idx >= BS * 2 * CC) return;
    int c = idx % (2 * CC); int b = idx / (2 * CC);
    g_ctx[idx] = (c < CC) ? xr[(size_t)b * NN * CC + c]
                          : xh[(size_t)b * NN * CC + (c - CC)];
}

__global__ void ie_gemm_kernel(const float* __restrict__ in, const float* __restrict__ W,
                               const float* __restrict__ bias, float* __restrict__ out,
                               int relu) {
    __shared__ float s_in[2 * CC];
    int b = blockIdx.y;
    int j = blockIdx.x * 128 + threadIdx.x;
    for (int t = threadIdx.x; t < 2 * CC; t += 128) s_in[t] = in[b * 2 * CC + t];
    __syncthreads();
    float a0 = 0.f, a1 = 0.f, a2 = 0.f, a3 = 0.f;
    for (int k = 0; k < 2 * CC; k += 4) {
        a0 += s_in[k + 0] * W[(size_t)(k + 0) * (2 * CC) + j];
        a1 += s_in[k + 1] * W[(size_t)(k + 1) * (2 * CC) + j];
        a2 += s_in[k + 2] * W[(size_t)(k + 2) * (2 * CC) + j];
        a3 += s_in[k + 3] * W[(size_t)(k + 3) * (2 * CC) + j];
    }
    float acc = (a0 + a1) + (a2 + a3) + bias[j];
    if (relu) acc = (acc > 0.f) ? acc : 0.f;
    out[b * 2 * CC + j] = acc;
}

__global__ void writeback_kernel(float* __restrict__ xr, float* __restrict__ xh) {
    int idx = blockIdx.x * blockDim.x + threadIdx.x;
    if (idx >= BS * 2 * CC) return;
    int c = idx % (2 * CC); int b = idx / (2 * CC);
    float v = g_ctx2[idx];
    bf16 hb, lb; split_bf(v, hb, lb);
    if (c < CC) {
        size_t o = (size_t)b * NN * CC + c;
        xr[o] = v; g_xrh[o] = hb; g_xrl[o] = lb;
    } else {
        size_t o = (size_t)b * NN * CC + (c - CC);
        xh[o] = v; g_xhh[o] = hb; g_xhl[o] = lb;
    }
}

// ---------------- launch ----------------
#define SYM(p, s) cudaGetSymbolAddress((void**)&p, s)

extern "C" void kernel_launch(void* const* d_in, const int* in_sizes, int n_in,
                              void* d_out, int out_size) {
    const float* spans  = (const float*)d_in[0];
    const float* svo    = (const float*)d_in[1];
    const float* pooled = (const float*)d_in[2];
    const int*   s2w    = (const int*)d_in[3];
    const int*   aug    = (const int*)d_in[4];
    const int*   punct  = (const int*)d_in[5];
    const float* w_rel  = (const float*)d_in[6];
    const float* w_root = (const float*)d_in[7];
    const float* b_rgcn = (const float*)d_in[8];
    const float* w_lin  = (const float*)d_in[9];
    const float* att_x  = (const float*)d_in[10];
    const float* att_e  = (const float*)d_in[11];
    const float* b_hgcn = (const float*)d_in[12];
    const float* ie_w1  = (const float*)d_in[13];
    const float* ie_b1  = (const float*)d_in[14];
    const float* ie_w2  = (const float*)d_in[15];
    const float* ie_b2  = (const float*)d_in[16];
    float* out = (float*)d_out;

    cudaFuncSetAttribute(gemm_kernel, cudaFuncAttributeMaxDynamicSharedMemorySize,
                         2 * STG_BYTES);

    float *p_ohp, *p_agg, *p_xroot, *p_xr, *p_xh, *p_an, *p_ae, *p_ctx, *p_h1, *p_ctx2;
    SYM(p_ohp, g_ohp); SYM(p_agg, g_agg); SYM(p_xroot, g_xroot);
    SYM(p_xr, g_xr); SYM(p_xh, g_xh); SYM(p_an, g_an); SYM(p_ae, g_ae);
    SYM(p_ctx, g_ctx); SYM(p_h1, g_h1); SYM(p_ctx2, g_ctx2);

    bf16 *x0h,*x0l,*eah,*eal,*wlh,*wll,*wrh,*wrl,*wth,*wtl,*xlh,*xll,*elh,*ell;
    bf16 *amnh,*amnl,*anmh,*anml,*msgh,*msgl,*xwh,*xwl,*Anh,*Anl,*xrh,*xrl,*xhh,*xhl;
    SYM(x0h, g_x0h); SYM(x0l, g_x0l); SYM(eah, g_eah); SYM(eal, g_eal);
    SYM(wlh, g_wlh); SYM(wll, g_wll); SYM(wrh, g_wrh); SYM(wrl, g_wrl);
    SYM(wth, g_wth); SYM(wtl, g_wtl); SYM(xlh, g_xlh); SYM(xll, g_xll);
    SYM(elh, g_elh); SYM(ell, g_ell); SYM(amnh, g_amnh); SYM(amnl, g_amnl);
    SYM(anmh, g_anmh); SYM(anml, g_anml); SYM(msgh, g_msgh); SYM(msgl, g_msgl);
    SYM(xwh, g_xwh); SYM(xwl, g_xwl); SYM(Anh, g_Anh); SYM(Anl, g_Anl);
    SYM(xrh, g_xrh); SYM(xrl, g_xrl); SYM(xhh, g_xhh); SYM(xhl, g_xhl);

    // ---- layer-invariant prep ----
    {
        size_t n;
        n = (size_t)BS*NN*CC;
        split_kernel<<<(int)((n+255)/256), 256>>>(spans, x0h, x0l, n);
        n = (size_t)LL*CC*HH*CC;
        split_kernel<<<(int)((n+255)/256), 256>>>(w_lin, wlh, wll, n);
        n = (size_t)LL*2*CC*CC;
        split_kernel<<<(int)((n+255)/256), 256>>>(w_rel, wrh, wrl, n);
        n = (size_t)LL*CC*CC;
        split_kernel<<<(int)((n+255)/256), 256>>>(w_root, wth, wtl, n);
    }
    prep_eattr_kernel<<<(BS * MM * CC + 255) / 256, 256>>>(pooled, svo);
    prep_deg_kernel<<<(BS * NN + BS * MM + 127) / 128, 128>>>(s2w);
    prep_anorm_kernel<<<(2 * BS * NN + 127) / 128, 128>>>(aug, punct);

    const bf16 *Axh_h = x0h, *Axh_l = x0l;   // x_h planes
    const bf16 *Axr_h = x0h, *Axr_l = x0l;   // x_r planes

    for (int l = 0; l < LL; l++) {
        float* xr_out = (l == LL - 1) ? out : p_xr;
        float* xh_out = (l == LL - 1) ? out + (size_t)BS * NN * CC : p_xh;
        const bf16* wlhp = wlh + (size_t)l * CC * HH * CC;
        const bf16* wllp = wll + (size_t)l * CC * HH * CC;

        // ---- HypergraphConv ----
        // xl planes = x_h @ w_lin   [8192,512]x[512,2048]
        gemm(Axh_h, Axh_l, wlhp, wllp, nullptr, xlh, xll,
             BS*NN, HH*CC, CC, CC, HH*CC, HH*CC, 1, 1, 0,0,0,0,0,0);
        // el planes = e_attr @ w_lin  [2080,512]x[512,2048]
        gemm(eah, eal, wlhp, wllp, nullptr, elh, ell,
             BS*MM, HH*CC, CC, CC, HH*CC, HH*CC, 1, 1, 0,0,0,0,0,0);
        attdot_kernel<<<BS*NN, 128>>>(xlh, xll, att_x + (size_t)l*HH*CC, p_an);
        attdot_kernel<<<BS*MM, 128>>>(elh, ell, att_e + (size_t)l*HH*CC, p_ae);
        alpha_kernel<<<BS*NN, 128>>>(s2w);
        // msge planes = alpha_mn @ xl   [65,256]x[256,512], batch (b,h)
        gemm(amnh, amnl, xlh, xll, nullptr, msgh, msgl,
             MM, CC, NN, NN, HH*CC, CC, BS*HH, HH,
             (long long)HH*MM*NN, (long long)MM*NN,
             (long long)NN*HH*CC, (long long)CC,
             (long long)HH*MM*CC, (long long)MM*CC);
        // ohp = (alpha_nm*invB) @ msge   [256,65(->96 zfill)]x[65,512]
        gemm(anmh, anml, msgh, msgl, p_ohp, nullptr, nullptr,
             NN, CC, MM, ALD, CC, CC, BS*HH, HH,
             (long long)HH*NN*ALD, (long long)NN*ALD,
             (long long)HH*MM*CC, (long long)MM*CC,
             (long long)HH*NN*CC, (long long)NN*CC);
        finalize_h_kernel<<<BS*NN, CC>>>(xh_out, b_hgcn + (size_t)l*CC);

        // ---- RGCN ----
        // xw planes = x_r @ w_rel[l,r]  (batch 2)
        gemm(Axr_h, Axr_l, wrh + (size_t)l*2*CC*CC, wrl + (size_t)l*2*CC*CC,
             nullptr, xwh, xwl,
             BS*NN, CC, CC, CC, CC, CC, 2, 1,
             0, 0, (long long)CC*CC, 0, (long long)BS*NN*CC, 0);
        // xroot = x_r @ w_root[l]
        gemm(Axr_h, Axr_l, wth + (size_t)l*CC*CC, wtl + (size_t)l*CC*CC,
             p_xroot, nullptr, nullptr,
             BS*NN, CC, CC, CC, CC, CC, 1, 1, 0,0,0,0,0,0);
        // agg[r][b] = Anorm[r][b] @ xw[r][b]   [256,256]x[256,512], batch 64
        gemm(Anh, Anl, xwh, xwl, p_agg, nullptr, nullptr,
             NN, CC, NN, NN, CC, CC, 2*BS, BS,
             (long long)BS*NN*NN, (long long)NN*NN,
             (long long)BS*NN*CC, (long long)NN*CC,
             (long long)BS*NN*CC, (long long)NN*CC);
        combine_rgcn_kernel<<<BS*NN, CC>>>(xr_out, b_rgcn + (size_t)l*CC);

        // ---- info exchange (row 0) ----
        build_ctx_kernel<<<(BS*2*CC + 255)/256, 256>>>(xr_out, xh_out);
        ie_gemm_kernel<<<dim3(2*CC/128, BS), 128>>>(
            p_ctx, ie_w1 + (size_t)l*2*CC*2*CC, ie_b1 + (size_t)l*2*CC, p_h1, 1);
        ie_gemm_kernel<<<dim3(2*CC/128, BS), 128>>>(
            p_h1, ie_w2 + (size_t)l*2*CC*2*CC, ie_b2 + (size_t)l*2*CC, p_ctx2, 0);
        writeback_kernel<<<(BS*2*CC + 255)/256, 256>>>(xr_out, xh_out);

        Axh_h = xhh; Axh_l = xhl;
        Axr_h = xrh; Axr_l = xrl;
    }
    (void)in_sizes; (void)n_in; (void)out_size;
}

// round 8
// speedup vs baseline: 3.1073x; 1.1534x over previous
#include <cuda_runtime.h>
#include <cuda_bf16.h>
#include <math.h>
#include <stdint.h>

#define BS 32
#define NN 256
#define EE 64
#define CC 512
#define HH 4
#define LL 2
#define MM 65
#define ALD 80   // padded lda for alpha_nm (160B rows, 16B aligned)

typedef __nv_bfloat16 bf16;

// ---------------- fp32 scratch ----------------
__device__ float g_ohp[(size_t)BS*HH*NN*CC];
__device__ float g_agg[(size_t)2*BS*NN*CC];
__device__ float g_xroot[(size_t)BS*NN*CC];
__device__ float g_xr[(size_t)BS*NN*CC];
__device__ float g_xh[(size_t)BS*NN*CC];
__device__ float g_ae[BS*MM*HH];
__device__ float g_vx[HH*CC];
__device__ float g_ve[HH*CC];
__device__ float g_invD[BS*NN];
__device__ float g_invB[BS*MM];
__device__ float g_ctx[BS*2*CC];
__device__ float g_h1[BS*2*CC];
__device__ float g_ctx2[BS*2*CC];

// ---------------- bf16 hi/lo planes ----------------
__device__ bf16 g_x0h[(size_t)BS*NN*CC],      g_x0l[(size_t)BS*NN*CC];
__device__ bf16 g_wlh[(size_t)LL*CC*HH*CC],   g_wll[(size_t)LL*CC*HH*CC];
__device__ bf16 g_wrh[(size_t)LL*2*CC*CC],    g_wrl[(size_t)LL*2*CC*CC];
__device__ bf16 g_wth[(size_t)LL*CC*CC],      g_wtl[(size_t)LL*CC*CC];
__device__ bf16 g_amnh[(size_t)BS*HH*MM*NN],  g_amnl[(size_t)BS*HH*MM*NN];
__device__ bf16 g_anmh[(size_t)BS*HH*NN*ALD], g_anml[(size_t)BS*HH*NN*ALD];
__device__ bf16 g_th[(size_t)BS*HH*MM*CC],    g_tl[(size_t)BS*HH*MM*CC];
__device__ bf16 g_msgh[(size_t)BS*HH*MM*CC],  g_msgl[(size_t)BS*HH*MM*CC];
__device__ bf16 g_xwh[(size_t)2*BS*NN*CC],    g_xwl[(size_t)2*BS*NN*CC];
__device__ bf16 g_Anh[(size_t)2*BS*NN*NN],    g_Anl[(size_t)2*BS*NN*NN];
__device__ bf16 g_xrh[(size_t)BS*NN*CC],      g_xrl[(size_t)BS*NN*CC];
__device__ bf16 g_xhh[(size_t)BS*NN*CC],      g_xhl[(size_t)BS*NN*CC];

// ---------------- helpers ----------------
__device__ __forceinline__ void split_bf(float x, bf16& h, bf16& l) {
    h = __float2bfloat16(x);
    l = __float2bfloat16(x - __bfloat162float(h));
}
__device__ __forceinline__ uint32_t pack_split_hi(float a, float b, uint32_t& lo_out) {
    bf16 h0, l0, h1, l1;
    split_bf(a, h0, l0); split_bf(b, h1, l1);
    __nv_bfloat162 hp; hp.x = h0; hp.y = h1;
    __nv_bfloat162 lp; lp.x = l0; lp.y = l1;
    uint32_t hv, lv;
    __builtin_memcpy(&hv, &hp, 4); __builtin_memcpy(&lv, &lp, 4);
    lo_out = lv; return hv;
}
__device__ __forceinline__ void mma_bf16(float* c, const uint32_t* a, const uint32_t* b) {
    asm volatile(
        "mma.sync.aligned.m16n8k16.row.col.f32.bf16.bf16.f32 "
        "{%0,%1,%2,%3}, {%4,%5,%6,%7}, {%8,%9}, {%0,%1,%2,%3};\n"
        : "+f"(c[0]), "+f"(c[1]), "+f"(c[2]), "+f"(c[3])
        : "r"(a[0]), "r"(a[1]), "r"(a[2]), "r"(a[3]), "r"(b[0]), "r"(b[1]));
}
__device__ __forceinline__ void cp16(uint32_t dst, const void* src, int sz) {
    asm volatile("cp.async.cg.shared.global [%0], [%1], 16, %2;\n"
                 :: "r"(dst), "l"(src), "r"(sz));
}
#define LDSM4(d0,d1,d2,d3,a) \
    asm volatile("ldmatrix.sync.aligned.m8n8.x4.shared.b16 {%0,%1,%2,%3}, [%4];" \
                 : "=r"(d0),"=r"(d1),"=r"(d2),"=r"(d3) : "r"(a))
#define LDSM4T(d0,d1,d2,d3,a) \
    asm volatile("ldmatrix.sync.aligned.m8n8.x4.trans.shared.b16 {%0,%1,%2,%3}, [%4];" \
                 : "=r"(d0),"=r"(d1),"=r"(d2),"=r"(d3) : "r"(a))

// ================= mma.sync split-bf16 GEMM =================
// C = (Ah+Al) @ (Bh+Bl) via AhBh + AhBl + AlBh, fp32 accum.
// Tile 128x128x32, 256 threads, 8 warps (2x4), warp tile 64x32, mma m16n8k16.
// Double-buffered cp.async, ldmatrix fragment loads, XOR-swizzled smem.
#define STG_BYTES 32768   // per stage: Ah 8K | Al 8K | Bh 8K | Bl 8K

__global__ __launch_bounds__(256, 2)
void gemm_kernel(const bf16* __restrict__ Ah, const bf16* __restrict__ Al,
                 const bf16* __restrict__ Bh, const bf16* __restrict__ Bl,
                 float* __restrict__ Cf, bf16* __restrict__ Chp, bf16* __restrict__ Clp,
                 int Mr, int Nc, int K, int lda, int ldb, int ldc,
                 int zdiv,
                 long long sA1, long long sA2,
                 long long sB1, long long sB2,
                 long long sC1, long long sC2)
{
    extern __shared__ __align__(128) unsigned char smem_raw[];
    uint32_t smem = (uint32_t)__cvta_generic_to_shared(smem_raw);

    int z = blockIdx.z;
    int z1 = z / zdiv, z2 = z % zdiv;
    long long offA = z1 * sA1 + z2 * sA2;
    long long offB = z1 * sB1 + z2 * sB2;
    long long offC = z1 * sC1 + z2 * sC2;
    Ah += offA; Al += offA; Bh += offB; Bl += offB;

    const int tid = threadIdx.x;
    const int warp = tid >> 5, lane = tid & 31;
    const int wm = warp >> 2, wn = warp & 3;
    const int g = lane >> 2, tg = lane & 3;
    const int rowBase = blockIdx.y * 128;
    const int colBase = blockIdx.x * 128;

    int am[2], ac[2], adst[2];
    int bk[2], bc[2], bdst[2];
    #pragma unroll
    for (int i = 0; i < 2; i++) {
        int q = i * 256 + tid;
        am[i] = q >> 2; ac[i] = q & 3;
        adst[i] = am[i] * 64 + ((ac[i] ^ (am[i] & 3)) << 4);
        bk[i] = q >> 4; bc[i] = q & 15;
        bdst[i] = bk[i] * 256 + ((bc[i] ^ (bk[i] & 7)) << 4);
    }

    int mloc = wm * 64 + (lane & 15);
    int addrA0 = mloc * 64 + (((lane >> 4) ^ (mloc & 3)) << 4);
    int kB = lane & 15;
    int cB0 = wn * 4 + (lane >> 4);
    int addrB0 = kB * 256 + ((cB0 ^ (kB & 7)) << 4);

    float acc[4][4][4];
    #pragma unroll
    for (int i = 0; i < 4; i++)
        #pragma unroll
        for (int j = 0; j < 4; j++)
            #pragma unroll
            for (int r = 0; r < 4; r++) acc[i][j][r] = 0.f;

    const int S = (K + 31) / 32;

    auto copy_stage = [&](int s, int buf) {
        int k0 = s * 32;
        uint32_t base = smem + buf * STG_BYTES;
        #pragma unroll
        for (int i = 0; i < 2; i++) {
            int gr = rowBase + am[i];
            int kk = k0 + ac[i] * 8;
            int rem = (gr < Mr) ? (K - kk) * 2 : 0;
            int sz = rem < 0 ? 0 : (rem > 16 ? 16 : rem);
            int grc = (gr < Mr) ? gr : 0;
            int kkc = (sz > 0) ? kk : 0;
            size_t so = (size_t)grc * lda + kkc;
            cp16(base + adst[i],        Ah + so, sz);
            cp16(base + 8192 + adst[i], Al + so, sz);
        }
        #pragma unroll
        for (int i = 0; i < 2; i++) {
            int kk = k0 + bk[i];
            int gc = colBase + bc[i] * 8;
            int ok = (kk < K) && (gc < Nc);
            int kkc = ok ? kk : 0;
            int gcc = ok ? gc : 0;
            size_t so = (size_t)kkc * ldb + gcc;
            cp16(base + 16384 + bdst[i], Bh + so, ok ? 16 : 0);
            cp16(base + 24576 + bdst[i], Bl + so, ok ? 16 : 0);
        }
    };

    copy_stage(0, 0);
    asm volatile("cp.async.commit_group;\n");

    for (int s = 0; s < S; s++) {
        if (s + 1 < S) copy_stage(s + 1, (s + 1) & 1);
        asm volatile("cp.async.commit_group;\n");
        asm volatile("cp.async.wait_group 1;\n");
        __syncthreads();

        uint32_t aH = smem + (s & 1) * STG_BYTES;
        uint32_t aL = aH + 8192;
        uint32_t bH = aH + 16384;
        uint32_t bL = aH + 24576;

        #pragma unroll
        for (int ks = 0; ks < 2; ks++) {
            int axor = ks * 32;
            int bofs = ks * 4096;
            uint32_t Afh[4][4], Bfh[4][2];
            #pragma unroll
            for (int mt = 0; mt < 4; mt++)
                LDSM4(Afh[mt][0], Afh[mt][1], Afh[mt][2], Afh[mt][3],
                      aH + (uint32_t)(((addrA0 + mt * 1024) ^ axor)));
            #pragma unroll
            for (int u = 0; u < 2; u++) {
                uint32_t d0, d1, d2, d3;
                LDSM4T(d0, d1, d2, d3, bH + (uint32_t)(((addrB0 ^ (u * 32)) + bofs)));
                Bfh[2*u][0] = d0; Bfh[2*u][1] = d1;
                Bfh[2*u+1][0] = d2; Bfh[2*u+1][1] = d3;
            }
            #pragma unroll
            for (int mt = 0; mt < 4; mt++)
                #pragma unroll
                for (int nt = 0; nt < 4; nt++)
                    mma_bf16(acc[mt][nt], Afh[mt], Bfh[nt]);

            #pragma unroll
            for (int u = 0; u < 2; u++) {
                uint32_t d0, d1, d2, d3;
                LDSM4T(d0, d1, d2, d3, bL + (uint32_t)(((addrB0 ^ (u * 32)) + bofs)));
                uint32_t Bfl0[2] = {d0, d1}, Bfl1[2] = {d2, d3};
                #pragma unroll
                for (int mt = 0; mt < 4; mt++) {
                    mma_bf16(acc[mt][2*u],   Afh[mt], Bfl0);
                    mma_bf16(acc[mt][2*u+1], Afh[mt], Bfl1);
                }
            }
            #pragma unroll
            for (int mt = 0; mt < 4; mt++) {
                uint32_t Afl[4];
                LDSM4(Afl[0], Afl[1], Afl[2], Afl[3],
                      aL + (uint32_t)(((addrA0 + mt * 1024) ^ axor)));
                #pragma unroll
                for (int nt = 0; nt < 4; nt++)
                    mma_bf16(acc[mt][nt], Afl, Bfh[nt]);
            }
        }
        __syncthreads();
    }

    float* Cw = Cf ? (Cf + offC) : nullptr;
    bf16* Chw = Chp ? (Chp + offC) : nullptr;
    bf16* Clw = Clp ? (Clp + offC) : nullptr;
    #pragma unroll
    for (int mt = 0; mt < 4; mt++) {
        int r0 = rowBase + wm * 64 + mt * 16 + g;
        #pragma unroll
        for (int half = 0; half < 2; half++) {
            int r = r0 + half * 8;
            if (r >= Mr) continue;
            #pragma unroll
            for (int nt = 0; nt < 4; nt++) {
                int c = colBase + wn * 32 + nt * 8 + tg * 2;
                if (c >= Nc) continue;
                float v0 = acc[mt][nt][half * 2];
                float v1 = acc[mt][nt][half * 2 + 1];
                size_t o = (size_t)r * ldc + c;
                if (Cw) { Cw[o] = v0; Cw[o + 1] = v1; }
                if (Chw) {
                    uint32_t lv, hv = pack_split_hi(v0, v1, lv);
                    *(uint32_t*)(Chw + o) = hv;
                    *(uint32_t*)(Clw + o) = lv;
                }
            }
        }
    }
}

static void gemm(const bf16* Ah, const bf16* Al, const bf16* Bh, const bf16* Bl,
                 float* Cf, bf16* Chp, bf16* Clp,
                 int Mr, int Nc, int K, int lda, int ldb, int ldc,
                 int batch, int zdiv,
                 long long sA1, long long sA2, long long sB1, long long sB2,
                 long long sC1, long long sC2)
{
    dim3 grid((Nc + 127) / 128, (Mr + 127) / 128, batch);
    gemm_kernel<<<grid, 256, 2 * STG_BYTES>>>(Ah, Al, Bh, Bl, Cf, Chp, Clp,
        Mr, Nc, K, lda, ldb, ldc, zdiv, sA1, sA2, sB1, sB2, sC1, sC2);
}

// ---------------- prep kernels ----------------
__global__ void split_kernel(const float* __restrict__ in, bf16* __restrict__ hi,
                             bf16* __restrict__ lo, size_t n) {
    size_t i = (size_t)blockIdx.x * blockDim.x + threadIdx.x;
    if (i >= n) return;
    bf16 h, l; split_bf(in[i], h, l);
    hi[i] = h; lo[i] = l;
}

__global__ void prep_deg_kernel(const int* __restrict__ s2w) {
    int idx = blockIdx.x * blockDim.x + threadIdx.x;
    if (idx < BS * NN) {
        const int* row = s2w + (size_t)idx * EE;
        int s = 1;
        for (int e = 0; e < EE; e++) s += row[e];
        g_invD[idx] = 1.f / (float)s;
    } else if (idx < BS * NN + BS * MM) {
        int t = idx - BS * NN;
        int m = t % MM, b = t / MM;
        if (m == 0) g_invB[t] = 1.f / (float)NN;
        else {
            int s = 0;
            for (int n = 0; n < NN; n++) s += s2w[((size_t)(b * NN + n)) * EE + (m - 1)];
            g_invB[t] = (s > 0) ? 1.f / (float)s : 0.f;
        }
    }
}

__global__ void prep_anorm_kernel(const int* __restrict__ aug,
                                  const int* __restrict__ punct) {
    int t = blockIdx.x * blockDim.x + threadIdx.x;
    if (t >= 2 * BS * NN) return;
    int j = t % NN;
    int b = (t / NN) % BS;
    int r = t / (NN * BS);
    int cnt = 0;
    for (int i = 0; i < NN; i++) {
        int a = aug[((size_t)(b * NN + i)) * NN + j];
        int v = r ? a : (punct[((size_t)(b * NN + i)) * NN + j] * (1 - a));
        cnt += v;
    }
    float val = cnt ? 1.f / (float)cnt : 0.f;
    bf16 vh, vl; split_bf(val, vh, vl);
    size_t base = ((size_t)(r * BS + b) * NN + j) * NN;
    for (int i = 0; i < NN; i++) {
        int a = aug[((size_t)(b * NN + i)) * NN + j];
        int v = r ? a : (punct[((size_t)(b * NN + i)) * NN + j] * (1 - a));
        g_Anh[base + i] = v ? vh : (bf16)__float2bfloat16(0.f);
        g_Anl[base + i] = v ? vl : (bf16)__float2bfloat16(0.f);
    }
}

// ---------------- attention path (att-vector folding) ----------------
// vx[h,k] = sum_c w_lin[l][k, h*C+c] * att_x[h,c]; ve likewise with att_e.
__global__ void compute_v_kernel(const float* __restrict__ wl,
                                 const float* __restrict__ attx,
                                 const float* __restrict__ atte) {
    int gw = (blockIdx.x * blockDim.x + threadIdx.x) >> 5;
    int lane = threadIdx.x & 31;
    if (gw >= 2 * HH * CC) return;
    int sel = gw / (HH * CC);
    int rem = gw % (HH * CC);
    int h = rem / CC, k = rem % CC;
    const float* att = (sel ? atte : attx) + h * CC;
    const float* row = wl + (size_t)k * (HH * CC) + h * CC;
    float acc = 0.f;
    for (int c = lane; c < CC; c += 32) acc += row[c] * att[c];
    #pragma unroll
    for (int o = 16; o; o >>= 1) acc += __shfl_xor_sync(0xffffffffu, acc, o);
    if (lane == 0) (sel ? g_ve : g_vx)[h * CC + k] = acc;
}

// a_e[b,m,h] = e_attr[b,m,:] . ve[h,:]  (e_attr read from pooled/svo directly)
__global__ void ae_kernel(const float* __restrict__ pooled,
                          const float* __restrict__ svo) {
    int bm = blockIdx.x;
    int h = threadIdx.x >> 5, lane = threadIdx.x & 31;
    int b = bm / MM, m = bm % MM;
    const float* e = (m == 0) ? (pooled + (size_t)b * CC)
                              : (svo + ((size_t)(b * EE + (m - 1))) * CC);
    const float* v = g_ve + h * CC;
    float acc = 0.f;
    for (int c = lane; c < CC; c += 32) acc += e[c] * v[c];
    #pragma unroll
    for (int o = 16; o; o >>= 1) acc += __shfl_xor_sync(0xffffffffu, acc, o);
    if (lane == 0) g_ae[bm * HH + h] = acc;
}

// a_n inline + masked softmax; writes alpha_mn planes and invB-scaled alpha_nm planes
__global__ void alpha_kernel(const bf16* __restrict__ Xh, const bf16* __restrict__ Xl,
                             const int* __restrict__ s2w) {
    int bn = blockIdx.x;
    int b = bn >> 8, n = bn & 255;
    int h = threadIdx.x >> 5, lane = threadIdx.x & 31;
    // a_n for this (b,n,h): dot of x row with vx[h]
    const bf16* xh = Xh + (size_t)bn * CC;
    const bf16* xl = Xl + (size_t)bn * CC;
    const float* v = g_vx + h * CC;
    float anv = 0.f;
    for (int c = lane; c < CC; c += 32)
        anv += (__bfloat162float(xh[c]) + __bfloat162float(xl[c])) * v[c];
    #pragma unroll
    for (int o = 16; o; o >>= 1) anv += __shfl_xor_sync(0xffffffffu, anv, o);

    float vv3[3]; int ok[3];
    #pragma unroll
    for (int s = 0; s < 3; s++) {
        int m = lane + s * 32;
        float vv = -1e30f; int o = 0;
        if (m < MM) {
            o = (m == 0) || (s2w[(size_t)bn * EE + (m - 1)] != 0);
            if (o) {
                float x = anv + g_ae[(b * MM + m) * HH + h];
                vv = (x > 0.f) ? x : 0.2f * x;
            }
        }
        vv3[s] = vv; ok[s] = o;
    }
    float mx = fmaxf(vv3[0], fmaxf(vv3[1], vv3[2]));
    #pragma unroll
    for (int o = 16; o; o >>= 1) mx = fmaxf(mx, __shfl_xor_sync(0xffffffffu, mx, o));
    float e3[3]; float sum = 0.f;
    #pragma unroll
    for (int s = 0; s < 3; s++) { e3[s] = ok[s] ? expf(vv3[s] - mx) : 0.f; sum += e3[s]; }
    #pragma unroll
    for (int o = 16; o; o >>= 1) sum += __shfl_xor_sync(0xffffffffu, sum, o);
    float inv = 1.f / sum;
    size_t z = (size_t)(b * HH + h);
    #pragma unroll
    for (int s = 0; s < 3; s++) {
        int m = lane + s * 32;
        if (m < MM) {
            float a = e3[s] * inv;
            bf16 hb, lb;
            split_bf(a, hb, lb);
            size_t o1 = (z * MM + m) * NN + n;
            g_amnh[o1] = hb; g_amnl[o1] = lb;
            float as = a * g_invB[b * MM + m];
            split_bf(as, hb, lb);
            size_t o2 = (z * NN + n) * ALD + m;
            g_anmh[o2] = hb; g_anml[o2] = lb;
        }
    }
}

__global__ void finalize_h_kernel(float* __restrict__ out, const float* __restrict__ bias) {
    int bn = blockIdx.x; int c = threadIdx.x;
    int b = bn >> 8, n = bn & 255;
    float s = 0.f;
    #pragma unroll
    for (int h = 0; h < HH; h++)
        s += g_ohp[(((size_t)(b * HH + h)) * NN + n) * CC + c];
    float v = s * 0.25f * g_invD[bn] + bias[c];
    v = (v > 0.f) ? v : 0.f;
    size_t o = (size_t)bn * CC + c;
    out[o] = v;
    bf16 hb, lb; split_bf(v, hb, lb);
    g_xhh[o] = hb; g_xhl[o] = lb;
}

__global__ void combine_rgcn_kernel(float* __restrict__ out, const float* __restrict__ bias) {
    int bj = blockIdx.x; int c = threadIdx.x;
    size_t o = (size_t)bj * CC + c;
    float v = g_agg[o] + g_agg[(size_t)BS * NN * CC + o] + g_xroot[o] + bias[c];
    v = (v > 0.f) ? v : 0.f;
    out[o] = v;
    bf16 hb, lb; split_bf(v, hb, lb);
    g_xrh[o] = hb; g_xrl[o] = lb;
}

// ---------------- info exchange ----------------
__global__ void build_ctx_kernel(const float* __restrict__ xr, const float* __restrict__ xh) {
    int idx = blockIdx.x * blockDim.x + threadIdx.x;
    if (idx >= BS * 2 * CC) return;
    int c = idx % (2 * CC); int b = idx / (2 * CC);
    g_ctx[idx] = (c < CC) ? xr[(size_t)b * NN * CC + c]
                          : xh[(size_t)b * NN * CC + (c - CC)];
}

__global__ void ie_gemm_kernel(const float* __restrict__ in, const float* __restrict__ W,
                               const float* __restrict__ bias, float* __restrict__ out,
                               int relu) {
    __shared__ float s_in[2 * CC];
    int b = blockIdx.y;
    int j = blockIdx.x * 128 + threadIdx.x;
    for (int t = threadIdx.x; t < 2 * CC; t += 128) s_in[t] = in[b * 2 * CC + t];
    __syncthreads();
    float a0 = 0.f, a1 = 0.f, a2 = 0.f, a3 = 0.f;
    for (int k = 0; k < 2 * CC; k += 4) {
        a0 += s_in[k + 0] * W[(size_t)(k + 0) * (2 * CC) + j];
        a1 += s_in[k + 1] * W[(size_t)(k + 1) * (2 * CC) + j];
        a2 += s_in[k + 2] * W[(size_t)(k + 2) * (2 * CC) + j];
        a3 += s_in[k + 3] * W[(size_t)(k + 3) * (2 * CC) + j];
    }
    float acc = (a0 + a1) + (a2 + a3) + bias[j];
    if (relu) acc = (acc > 0.f) ? acc : 0.f;
    out[b * 2 * CC + j] = acc;
}

__global__ void writeback_kernel(float* __restrict__ xr, float* __restrict__ xh) {
    int idx = blockIdx.x * blockDim.x + threadIdx.x;
    if (idx >= BS * 2 * CC) return;
    int c = idx % (2 * CC); int b = idx / (2 * CC);
    float v = g_ctx2[idx];
    bf16 hb, lb; split_bf(v, hb, lb);
    if (c < CC) {
        size_t o = (size_t)b * NN * CC + c;
        xr[o] = v; g_xrh[o] = hb; g_xrl[o] = lb;
    } else {
        size_t o = (size_t)b * NN * CC + (c - CC);
        xh[o] = v; g_xhh[o] = hb; g_xhl[o] = lb;
    }
}

// ---------------- launch ----------------
#define SYM(p, s) cudaGetSymbolAddress((void**)&p, s)

extern "C" void kernel_launch(void* const* d_in, const int* in_sizes, int n_in,
                              void* d_out, int out_size) {
    const float* spans  = (const float*)d_in[0];
    const float* svo    = (const float*)d_in[1];
    const float* pooled = (const float*)d_in[2];
    const int*   s2w    = (const int*)d_in[3];
    const int*   aug    = (const int*)d_in[4];
    const int*   punct  = (const int*)d_in[5];
    const float* w_rel  = (const float*)d_in[6];
    const float* w_root = (const float*)d_in[7];
    const float* b_rgcn = (const float*)d_in[8];
    const float* w_lin  = (const float*)d_in[9];
    const float* att_x  = (const float*)d_in[10];
    const float* att_e  = (const float*)d_in[11];
    const float* b_hgcn = (const float*)d_in[12];
    const float* ie_w1  = (const float*)d_in[13];
    const float* ie_b1  = (const float*)d_in[14];
    const float* ie_w2  = (const float*)d_in[15];
    const float* ie_b2  = (const float*)d_in[16];
    float* out = (float*)d_out;

    cudaFuncSetAttribute(gemm_kernel, cudaFuncAttributeMaxDynamicSharedMemorySize,
                         2 * STG_BYTES);

    float *p_ohp, *p_agg, *p_xroot, *p_xr, *p_xh, *p_ctx, *p_h1, *p_ctx2;
    SYM(p_ohp, g_ohp); SYM(p_agg, g_agg); SYM(p_xroot, g_xroot);
    SYM(p_xr, g_xr); SYM(p_xh, g_xh);
    SYM(p_ctx, g_ctx); SYM(p_h1, g_h1); SYM(p_ctx2, g_ctx2);

    bf16 *x0h,*x0l,*wlh,*wll,*wrh,*wrl,*wth,*wtl;
    bf16 *amnh,*amnl,*anmh,*anml,*th,*tl,*msgh,*msgl,*xwh,*xwl,*Anh,*Anl;
    bf16 *xrh,*xrl,*xhh,*xhl;
    SYM(x0h, g_x0h); SYM(x0l, g_x0l);
    SYM(wlh, g_wlh); SYM(wll, g_wll); SYM(wrh, g_wrh); SYM(wrl, g_wrl);
    SYM(wth, g_wth); SYM(wtl, g_wtl);
    SYM(amnh, g_amnh); SYM(amnl, g_amnl);
    SYM(anmh, g_anmh); SYM(anml, g_anml);
    SYM(th, g_th); SYM(tl, g_tl);
    SYM(msgh, g_msgh); SYM(msgl, g_msgl);
    SYM(xwh, g_xwh); SYM(xwl, g_xwl); SYM(Anh, g_Anh); SYM(Anl, g_Anl);
    SYM(xrh, g_xrh); SYM(xrl, g_xrl); SYM(xhh, g_xhh); SYM(xhl, g_xhl);

    // ---- layer-invariant prep ----
    {
        size_t n;
        n = (size_t)BS*NN*CC;
        split_kernel<<<(int)((n+255)/256), 256>>>(spans, x0h, x0l, n);
        n = (size_t)LL*CC*HH*CC;
        split_kernel<<<(int)((n+255)/256), 256>>>(w_lin, wlh, wll, n);
        n = (size_t)LL*2*CC*CC;
        split_kernel<<<(int)((n+255)/256), 256>>>(w_rel, wrh, wrl, n);
        n = (size_t)LL*CC*CC;
        split_kernel<<<(int)((n+255)/256), 256>>>(w_root, wth, wtl, n);
    }
    prep_deg_kernel<<<(BS * NN + BS * MM + 127) / 128, 128>>>(s2w);
    prep_anorm_kernel<<<(2 * BS * NN + 127) / 128, 128>>>(aug, punct);

    const bf16 *Axh_h = x0h, *Axh_l = x0l;
    const bf16 *Axr_h = x0h, *Axr_l = x0l;

    for (int l = 0; l < LL; l++) {
        float* xr_out = (l == LL - 1) ? out : p_xr;
        float* xh_out = (l == LL - 1) ? out + (size_t)BS * NN * CC : p_xh;
        const float* wlf = w_lin + (size_t)l * CC * HH * CC;
        const bf16* wlhp = wlh + (size_t)l * CC * HH * CC;
        const bf16* wllp = wll + (size_t)l * CC * HH * CC;

        // ---- HypergraphConv (att-vector folded) ----
        compute_v_kernel<<<(2 * HH * CC * 32 + 255) / 256, 256>>>(
            wlf, att_x + (size_t)l * HH * CC, att_e + (size_t)l * HH * CC);
        ae_kernel<<<BS * MM, 128>>>(pooled, svo);
        alpha_kernel<<<BS * NN, 128>>>(Axh_h, Axh_l, s2w);
        // t[b,h] = alpha_mn[b,h] @ x_h[b]   [65,256]x[256,512], batch (b,h)
        gemm(amnh, amnl, Axh_h, Axh_l, nullptr, th, tl,
             MM, CC, NN, NN, CC, CC, BS*HH, HH,
             (long long)HH*MM*NN, (long long)MM*NN,
             (long long)NN*CC, 0,
             (long long)HH*MM*CC, (long long)MM*CC);
        // msg[b,h] = t[b,h] @ Wl[:, h-block]   [65,512]x[512,512], batch (b,h)
        gemm(th, tl, wlhp, wllp, nullptr, msgh, msgl,
             MM, CC, CC, CC, HH*CC, CC, BS*HH, HH,
             (long long)HH*MM*CC, (long long)MM*CC,
             0, (long long)CC,
             (long long)HH*MM*CC, (long long)MM*CC);
        // ohp = (alpha_nm*invB) @ msg   [256,65]x[65,512], batch (b,h)
        gemm(anmh, anml, msgh, msgl, p_ohp, nullptr, nullptr,
             NN, CC, MM, ALD, CC, CC, BS*HH, HH,
             (long long)HH*NN*ALD, (long long)NN*ALD,
             (long long)HH*MM*CC, (long long)MM*CC,
             (long long)HH*NN*CC, (long long)NN*CC);
        finalize_h_kernel<<<BS*NN, CC>>>(xh_out, b_hgcn + (size_t)l*CC);

        // ---- RGCN ----
        // xw planes = x_r @ w_rel[l,r]  (batch 2)
        gemm(Axr_h, Axr_l, wrh + (size_t)l*2*CC*CC, wrl + (size_t)l*2*CC*CC,
             nullptr, xwh, xwl,
             BS*NN, CC, CC, CC, CC, CC, 2, 1,
             0, 0, (long long)CC*CC, 0, (long long)BS*NN*CC, 0);
        // xroot = x_r @ w_root[l]
        gemm(Axr_h, Axr_l, wth + (size_t)l*CC*CC, wtl + (size_t)l*CC*CC,
             p_xroot, nullptr, nullptr,
             BS*NN, CC, CC, CC, CC, CC, 1, 1, 0,0,0,0,0,0);
        // agg[r][b] = Anorm[r][b] @ xw[r][b]   [256,256]x[256,512], batch 64
        gemm(Anh, Anl, xwh, xwl, p_agg, nullptr, nullptr,
             NN, CC, NN, NN, CC, CC, 2*BS, BS,
             (long long)BS*NN*NN, (long long)NN*NN,
             (long long)BS*NN*CC, (long long)NN*CC,
             (long long)BS*NN*CC, (long long)NN*CC);
        combine_rgcn_kernel<<<BS*NN, CC>>>(xr_out, b_rgcn + (size_t)l*CC);

        // ---- info exchange (row 0) ----
        build_ctx_kernel<<<(BS*2*CC + 255)/256, 256>>>(xr_out, xh_out);
        ie_gemm_kernel<<<dim3(2*CC/128, BS), 128>>>(
            p_ctx, ie_w1 + (size_t)l*2*CC*2*CC, ie_b1 + (size_t)l*2*CC, p_h1, 1);
        ie_gemm_kernel<<<dim3(2*CC/128, BS), 128>>>(
            p_h1, ie_w2 + (size_t)l*2*CC*2*CC, ie_b2 + (size_t)l*2*CC, p_ctx2, 0);
        writeback_kernel<<<(BS*2*CC + 255)/256, 256>>>(xr_out, xh_out);

        Axh_h = xhh; Axh_l = xhl;
        Axr_h = xrh; Axr_l = xrl;
    }
    (void)in_sizes; (void)n_in; (void)out_size;
}